// round 1
// baseline (speedup 1.0000x reference)
#include <cuda_runtime.h>
#include <math.h>

// ---- problem constants (fixed shapes for this dataset) ----
#define VV 100000
#define EE 400000
#define GG 200
#define NFEAT 74
#define NEFEAT 12
#define NGMAX 8192

// ---- scratch (device globals; no allocations allowed) ----
__device__ float    g_hv [VV * GG];        // hv_new / nf (node state)
__device__ float    g_he1[EE * GG];        // he1 per edge
__device__ float    g_c  [VV * GG];        // context accumulation
__device__ float    g_hvp[VV * GG];        // hvp per node (GNN layers)
__device__ float    g_gi [VV * 3 * GG];    // GRU gi
__device__ float    g_gh [VV * 3 * GG];    // GRU gh
__device__ float    g_mask[VV];
__device__ float    g_d0[VV];
__device__ float    g_d1[VV];
__device__ unsigned g_nmax[VV];
__device__ float    g_nsum[VV];
__device__ float    g_logit[EE];
__device__ float    g_att[EE];
__device__ float    g_gsum[NGMAX];

// ---- small helpers ----
__device__ __forceinline__ float lreluf(float x) { return x > 0.f ? x : 0.01f * x; }
__device__ __forceinline__ float sigmoidf_(float x) { return 1.f / (1.f + expf(-x)); }
__device__ __forceinline__ unsigned fenc(float f) {
    unsigned b = __float_as_uint(f);
    return (b & 0x80000000u) ? ~b : (b | 0x80000000u);
}
__device__ __forceinline__ float fdec(unsigned u) {
    unsigned b = (u & 0x80000000u) ? (u & 0x7fffffffu) : ~u;
    return __uint_as_float(b);
}
__device__ __forceinline__ float warp_sum(float v) {
    #pragma unroll
    for (int o = 16; o; o >>= 1) v += __shfl_down_sync(0xffffffffu, v, o);
    return v;
}

// ---- fill kernels (graph-capturable zeroing) ----
__global__ void fill_f_kernel(float* p, float v, int n) {
    int i = blockIdx.x * blockDim.x + threadIdx.x;
    if (i < n) p[i] = v;
}
__global__ void fill_u_kernel(unsigned* p, unsigned v, int n) {
    int i = blockIdx.x * blockDim.x + threadIdx.x;
    if (i < n) p[i] = v;
}

// ---- mask: 1/(sum(h[:,-4:])*(1-h[:,0])) - 1 ----
__global__ void mask_kernel(const float* __restrict__ nf, float* __restrict__ mask, int V) {
    int v = blockIdx.x * blockDim.x + threadIdx.x;
    if (v >= V) return;
    const float* r = nf + (long)v * NFEAT;
    float s = r[NFEAT - 4] + r[NFEAT - 3] + r[NFEAT - 2] + r[NFEAT - 1];
    float m = s * (1.f - r[0]);
    mask[v] = 1.f / m - 1.f;
}

// ---- generic tiled SGEMM ----
// AM: 0=direct, 1=elu(direct), 2=edge concat [node_feats[src[e]] | edge_feats[e]] (K=86)
// EPI: 0=store(+bias), 1=lrelu(+bias), 2=(acc+bias)*ascale[row] atomicAdd into C[dstidx[row]*N+col]
#define BM 64
#define BN 64
#define BKK 16
template<int AM, int EPI>
__global__ __launch_bounds__(256)
void sgemm_kernel(const float* __restrict__ A, int lda,
                  const float* __restrict__ B,        // K x N row-major
                  const float* __restrict__ bias,     // N
                  float* __restrict__ C,
                  int M, int N, int K,
                  const float* __restrict__ nodef, const float* __restrict__ edgef,
                  const int* __restrict__ src,
                  const float* __restrict__ ascale, const int* __restrict__ dstidx)
{
    __shared__ float As[BKK][BM + 1];
    __shared__ float Bs[BKK][BN];
    int tid = threadIdx.x;
    int tx = tid & 15, ty = tid >> 4;
    int row0 = blockIdx.y * BM;
    int col0 = blockIdx.x * BN;
    float acc[4][4] = {};

    for (int k0 = 0; k0 < K; k0 += BKK) {
        // load A tile (64 rows x 16 k)
        #pragma unroll
        for (int i = 0; i < 4; i++) {
            int lin = tid + i * 256;
            int r = lin >> 4;
            int kk = lin & 15;
            int gr = row0 + r, gk = k0 + kk;
            float v = 0.f;
            if (gr < M && gk < K) {
                if (AM == 2) {
                    int s = src[gr];
                    v = (gk < NFEAT) ? nodef[(long)s * NFEAT + gk]
                                     : edgef[(long)gr * NEFEAT + (gk - NFEAT)];
                } else {
                    v = A[(long)gr * lda + gk];
                    if (AM == 1) v = v > 0.f ? v : expm1f(v);
                }
            }
            As[kk][r] = v;
        }
        // load B tile (16 k x 64 cols)
        #pragma unroll
        for (int i = 0; i < 4; i++) {
            int lin = tid + i * 256;
            int kk = lin >> 6;
            int n = lin & 63;
            int gk = k0 + kk, gn = col0 + n;
            Bs[kk][n] = (gk < K && gn < N) ? B[(long)gk * N + gn] : 0.f;
        }
        __syncthreads();
        #pragma unroll
        for (int kk = 0; kk < BKK; kk++) {
            float a0 = As[kk][ty * 4 + 0];
            float a1 = As[kk][ty * 4 + 1];
            float a2 = As[kk][ty * 4 + 2];
            float a3 = As[kk][ty * 4 + 3];
            float4 b = *(const float4*)&Bs[kk][tx * 4];
            acc[0][0] += a0 * b.x; acc[0][1] += a0 * b.y; acc[0][2] += a0 * b.z; acc[0][3] += a0 * b.w;
            acc[1][0] += a1 * b.x; acc[1][1] += a1 * b.y; acc[1][2] += a1 * b.z; acc[1][3] += a1 * b.w;
            acc[2][0] += a2 * b.x; acc[2][1] += a2 * b.y; acc[2][2] += a2 * b.z; acc[2][3] += a2 * b.w;
            acc[3][0] += a3 * b.x; acc[3][1] += a3 * b.y; acc[3][2] += a3 * b.z; acc[3][3] += a3 * b.w;
        }
        __syncthreads();
    }

    #pragma unroll
    for (int ii = 0; ii < 4; ii++) {
        int gr = row0 + ty * 4 + ii;
        if (gr >= M) continue;
        float as_ = 0.f; int dd = 0;
        if (EPI == 2) { as_ = ascale[gr]; dd = dstidx[gr]; }
        #pragma unroll
        for (int jj = 0; jj < 4; jj++) {
            int gn = col0 + tx * 4 + jj;
            if (gn >= N) continue;
            float v = acc[ii][jj] + bias[gn];
            if (EPI == 1) v = lreluf(v);
            if (EPI == 2) atomicAdd(&C[(long)dd * N + gn], v * as_);
            else          C[(long)gr * N + gn] = v;
        }
    }
}

// ---- per-node dot(s): out0 = X[v].w0, out1 = X[v].w1 (w1 optional) ----
__global__ void node_dots_kernel(const float* __restrict__ X,
                                 const float* __restrict__ w0, const float* __restrict__ w1,
                                 float* __restrict__ out0, float* __restrict__ out1, int V)
{
    int warp = (blockIdx.x * blockDim.x + threadIdx.x) >> 5;
    int lane = threadIdx.x & 31;
    if (warp >= V) return;
    const float* x = X + (long)warp * GG;
    float s0 = 0.f, s1 = 0.f;
    for (int j = lane; j < GG; j += 32) {
        float xv = x[j];
        s0 += xv * w0[j];
        if (w1) s1 += xv * w1[j];
    }
    s0 = warp_sum(s0);
    if (w1) s1 = warp_sum(s1);
    if (lane == 0) {
        out0[warp] = s0;
        if (w1) out1[warp] = s1;
    }
}

// ---- context edge logit: lrelu(d0[dst] + he1[e].w + b) ----
__global__ void edge_ctx_logit_kernel(const float* __restrict__ he1,
                                      const float* __restrict__ w, const float* __restrict__ b,
                                      const float* __restrict__ d0, const int* __restrict__ dst,
                                      float* __restrict__ logit, int E)
{
    int warp = (blockIdx.x * blockDim.x + threadIdx.x) >> 5;
    int lane = threadIdx.x & 31;
    if (warp >= E) return;
    const float* x = he1 + (long)warp * GG;
    float s = 0.f;
    for (int j = lane; j < GG; j += 32) s += x[j] * w[j];
    s = warp_sum(s);
    if (lane == 0) logit[warp] = lreluf(d0[dst[warp]] + s + b[0]);
}

// ---- layer edge logit: lrelu(d0[dst] + d1[src] + b) ----
__global__ void edge_layer_logit_kernel(const float* __restrict__ d0, const float* __restrict__ d1,
                                        const int* __restrict__ src, const int* __restrict__ dst,
                                        const float* __restrict__ b, float* __restrict__ logit, int E)
{
    int e = blockIdx.x * blockDim.x + threadIdx.x;
    if (e >= E) return;
    logit[e] = lreluf(d0[dst[e]] + d1[src[e]] + b[0]);
}

// ---- edge softmax over dst (atomics) ----
__global__ void smax_max_kernel(const float* __restrict__ logit, const int* __restrict__ dst,
                                unsigned* __restrict__ nmax, int E)
{
    int e = blockIdx.x * blockDim.x + threadIdx.x;
    if (e >= E) return;
    atomicMax(&nmax[dst[e]], fenc(logit[e]));
}
__global__ void smax_expsum_kernel(const float* __restrict__ logit, const int* __restrict__ dst,
                                   const unsigned* __restrict__ nmax, float* __restrict__ nsum,
                                   float* __restrict__ a, int E)
{
    int e = blockIdx.x * blockDim.x + threadIdx.x;
    if (e >= E) return;
    int d = dst[e];
    float v = expf(logit[e] - fdec(nmax[d]));
    a[e] = v;
    atomicAdd(&nsum[d], v);
}
__global__ void smax_norm_kernel(const int* __restrict__ dst, const float* __restrict__ nsum,
                                 float* __restrict__ a, int E)
{
    int e = blockIdx.x * blockDim.x + threadIdx.x;
    if (e >= E) return;
    a[e] /= nsum[dst[e]];
}

// ---- GNN layer context scatter: c[dst] += a[e] * hvp[src] ----
__global__ void scatter_c_kernel(const float* __restrict__ hvp, const float* __restrict__ a,
                                 const int* __restrict__ src, const int* __restrict__ dst,
                                 float* __restrict__ c, int E)
{
    int warp = (blockIdx.x * blockDim.x + threadIdx.x) >> 5;
    int lane = threadIdx.x & 31;
    if (warp >= E) return;
    float av = a[warp];
    const float* hs = hvp + (long)src[warp] * GG;
    float* cd = c + (long)dst[warp] * GG;
    for (int j = lane; j < GG; j += 32) atomicAdd(&cd[j], av * hs[j]);
}

// ---- GRU gates + relu, in-place h update ----
__global__ void gru_gates_kernel(const float* __restrict__ gi, const float* __restrict__ gh,
                                 float* __restrict__ h, int V)
{
    int idx = blockIdx.x * blockDim.x + threadIdx.x;
    if (idx >= V * GG) return;
    int v = idx / GG, j = idx - v * GG;
    const float* gvi = gi + (long)v * 3 * GG;
    const float* gvh = gh + (long)v * 3 * GG;
    float r = sigmoidf_(gvi[j]          + gvh[j]);
    float z = sigmoidf_(gvi[j + GG]     + gvh[j + GG]);
    float n = tanhf   (gvi[j + 2 * GG] + r * gvh[j + 2 * GG]);
    float hv = h[idx];
    float o = (1.f - z) * n + z * hv;
    h[idx] = o > 0.f ? o : 0.f;
}

// ---- readout: atom_pka + graph 10^ sum ----
__global__ void pred_kernel(const float* __restrict__ nf, const float* __restrict__ predW,
                            const float* __restrict__ predb, const float* __restrict__ mask,
                            const int* __restrict__ gids, float* __restrict__ out_atom,
                            float* __restrict__ gsum, int V)
{
    int warp = (blockIdx.x * blockDim.x + threadIdx.x) >> 5;
    int lane = threadIdx.x & 31;
    if (warp >= V) return;
    const float* x = nf + (long)warp * GG;
    float s = 0.f;
    for (int j = lane; j < GG; j += 32) s += x[j] * predW[j];
    s = warp_sum(s);
    if (lane == 0) {
        float ap = s + predb[0] + mask[warp];   // atom_pka_out
        out_atom[warp] = ap;
        atomicAdd(&gsum[gids[warp]], exp10f(-ap));
    }
}
__global__ void final_kernel(const float* __restrict__ gsum, float* __restrict__ out, int NG) {
    int g = blockIdx.x * blockDim.x + threadIdx.x;
    if (g >= NG) return;
    out[g] = -log10f(gsum[g]);
}

// ---- host ----
static inline int cdiv(int a, int b) { return (a + b - 1) / b; }

extern "C" void kernel_launch(void* const* d_in, const int* in_sizes, int n_in,
                              void* d_out, int out_size)
{
    const float* node_feats = (const float*)d_in[0];
    const float* edge_feats = (const float*)d_in[1];
    const float* pn_W  = (const float*)d_in[2];
    const float* pn_b  = (const float*)d_in[3];
    const float* pe1_W = (const float*)d_in[4];
    const float* pe1_b = (const float*)d_in[5];
    const float* pe2_W = (const float*)d_in[6];
    const float* pe2_b = (const float*)d_in[7];
    const float* et_W  = (const float*)d_in[8];
    const float* et_b  = (const float*)d_in[9];
    const float* gru0_Wih = (const float*)d_in[10];
    const float* gru0_Whh = (const float*)d_in[11];
    const float* gru0_bih = (const float*)d_in[12];
    const float* gru0_bhh = (const float*)d_in[13];
    const float* gnn_pe_W = (const float*)d_in[14];   // (L,400,1)
    const float* gnn_pe_b = (const float*)d_in[15];   // (L,1)
    const float* gnn_pn_W = (const float*)d_in[16];   // (L,200,200)
    const float* gnn_pn_b = (const float*)d_in[17];   // (L,200)
    const float* gnn_gru_Wih = (const float*)d_in[18]; // (L,200,600)
    const float* gnn_gru_Whh = (const float*)d_in[19];
    const float* gnn_gru_bih = (const float*)d_in[20]; // (L,600)
    const float* gnn_gru_bhh = (const float*)d_in[21];
    const float* pred_W = (const float*)d_in[22];
    const float* pred_b = (const float*)d_in[23];
    const int* srci = (const int*)d_in[24];
    const int* dsti = (const int*)d_in[25];
    const int* gids = (const int*)d_in[26];

    int V = in_sizes[0] / NFEAT;
    int E = in_sizes[24];
    int NG = out_size - V;
    float* out = (float*)d_out;
    int L = in_sizes[15];  // gnn_pe_b has L elements

    float *hv, *he1, *c, *hvp, *gi, *gh, *maskp, *d0, *d1, *nsum, *logit, *att, *gsum;
    unsigned* nmax;
    cudaGetSymbolAddress((void**)&hv,   g_hv);
    cudaGetSymbolAddress((void**)&he1,  g_he1);
    cudaGetSymbolAddress((void**)&c,    g_c);
    cudaGetSymbolAddress((void**)&hvp,  g_hvp);
    cudaGetSymbolAddress((void**)&gi,   g_gi);
    cudaGetSymbolAddress((void**)&gh,   g_gh);
    cudaGetSymbolAddress((void**)&maskp,g_mask);
    cudaGetSymbolAddress((void**)&d0,   g_d0);
    cudaGetSymbolAddress((void**)&d1,   g_d1);
    cudaGetSymbolAddress((void**)&nmax, g_nmax);
    cudaGetSymbolAddress((void**)&nsum, g_nsum);
    cudaGetSymbolAddress((void**)&logit,g_logit);
    cudaGetSymbolAddress((void**)&att,  g_att);
    cudaGetSymbolAddress((void**)&gsum, g_gsum);

    dim3 blk(256);

    // mask
    mask_kernel<<<cdiv(V, 256), blk>>>(node_feats, maskp, V);

    // hv_new = lrelu(node_feats @ pn_W + pn_b)
    {
        dim3 g(cdiv(GG, BN), cdiv(V, BM));
        sgemm_kernel<0, 1><<<g, blk>>>(node_feats, NFEAT, pn_W, pn_b, hv,
                                       V, GG, NFEAT, nullptr, nullptr, nullptr, nullptr, nullptr);
    }
    // he1 = lrelu(concat(node_feats[src], edge_feats) @ pe1_W + pe1_b)
    {
        dim3 g(cdiv(GG, BN), cdiv(E, BM));
        sgemm_kernel<2, 1><<<g, blk>>>(nullptr, 0, pe1_W, pe1_b, he1,
                                       E, GG, NFEAT + NEFEAT, node_feats, edge_feats, srci,
                                       nullptr, nullptr);
    }
    // d0 = hv . pe2_W[0:200]
    node_dots_kernel<<<cdiv(V, 8), blk>>>(hv, pe2_W, nullptr, d0, nullptr, V);
    // logits
    edge_ctx_logit_kernel<<<cdiv(E, 8), blk>>>(he1, pe2_W + GG, pe2_b, d0, dsti, logit, E);
    // edge softmax
    fill_u_kernel<<<cdiv(V, 256), blk>>>(nmax, 0u, V);
    fill_f_kernel<<<cdiv(V, 256), blk>>>(nsum, 0.f, V);
    smax_max_kernel<<<cdiv(E, 256), blk>>>(logit, dsti, nmax, E);
    smax_expsum_kernel<<<cdiv(E, 256), blk>>>(logit, dsti, nmax, nsum, att, E);
    smax_norm_kernel<<<cdiv(E, 256), blk>>>(dsti, nsum, att, E);
    // c = segment_sum(a * (he1 @ et_W + et_b), dst)
    fill_f_kernel<<<cdiv(V * GG, 256), blk>>>(c, 0.f, V * GG);
    {
        dim3 g(cdiv(GG, BN), cdiv(E, BM));
        sgemm_kernel<0, 2><<<g, blk>>>(he1, GG, et_W, et_b, c,
                                       E, GG, GG, nullptr, nullptr, nullptr, att, dsti);
    }
    // GRU0: gi = elu(c)@Wih+bih, gh = hv@Whh+bhh, gates -> hv (nf)
    {
        dim3 g(cdiv(3 * GG, BN), cdiv(V, BM));
        sgemm_kernel<1, 0><<<g, blk>>>(c, GG, gru0_Wih, gru0_bih, gi,
                                       V, 3 * GG, GG, nullptr, nullptr, nullptr, nullptr, nullptr);
        sgemm_kernel<0, 0><<<g, blk>>>(hv, GG, gru0_Whh, gru0_bhh, gh,
                                       V, 3 * GG, GG, nullptr, nullptr, nullptr, nullptr, nullptr);
    }
    gru_gates_kernel<<<cdiv(V * GG, 256), blk>>>(gi, gh, hv, V);

    // GNN layers
    for (int l = 0; l < L; l++) {
        node_dots_kernel<<<cdiv(V, 8), blk>>>(hv, gnn_pe_W + (long)l * 2 * GG,
                                              gnn_pe_W + (long)l * 2 * GG + GG, d0, d1, V);
        edge_layer_logit_kernel<<<cdiv(E, 256), blk>>>(d0, d1, srci, dsti, gnn_pe_b + l, logit, E);
        fill_u_kernel<<<cdiv(V, 256), blk>>>(nmax, 0u, V);
        fill_f_kernel<<<cdiv(V, 256), blk>>>(nsum, 0.f, V);
        smax_max_kernel<<<cdiv(E, 256), blk>>>(logit, dsti, nmax, E);
        smax_expsum_kernel<<<cdiv(E, 256), blk>>>(logit, dsti, nmax, nsum, att, E);
        smax_norm_kernel<<<cdiv(E, 256), blk>>>(dsti, nsum, att, E);
        // hvp = nf @ pn_W[l] + b
        {
            dim3 g(cdiv(GG, BN), cdiv(V, BM));
            sgemm_kernel<0, 0><<<g, blk>>>(hv, GG, gnn_pn_W + (long)l * GG * GG,
                                           gnn_pn_b + (long)l * GG, hvp,
                                           V, GG, GG, nullptr, nullptr, nullptr, nullptr, nullptr);
        }
        fill_f_kernel<<<cdiv(V * GG, 256), blk>>>(c, 0.f, V * GG);
        scatter_c_kernel<<<cdiv(E, 8), blk>>>(hvp, att, srci, dsti, c, E);
        {
            dim3 g(cdiv(3 * GG, BN), cdiv(V, BM));
            sgemm_kernel<1, 0><<<g, blk>>>(c, GG, gnn_gru_Wih + (long)l * GG * 3 * GG,
                                           gnn_gru_bih + (long)l * 3 * GG, gi,
                                           V, 3 * GG, GG, nullptr, nullptr, nullptr, nullptr, nullptr);
            sgemm_kernel<0, 0><<<g, blk>>>(hv, GG, gnn_gru_Whh + (long)l * GG * 3 * GG,
                                           gnn_gru_bhh + (long)l * 3 * GG, gh,
                                           V, 3 * GG, GG, nullptr, nullptr, nullptr, nullptr, nullptr);
        }
        gru_gates_kernel<<<cdiv(V * GG, 256), blk>>>(gi, gh, hv, V);
    }

    // readout
    fill_f_kernel<<<cdiv(NG, 256), blk>>>(gsum, 0.f, NG);
    pred_kernel<<<cdiv(V, 8), blk>>>(hv, pred_W, pred_b, maskp, gids, out + NG, gsum, V);
    final_kernel<<<cdiv(NG, 256), blk>>>(gsum, out, NG);
}

// round 2
// speedup vs baseline: 1.8853x; 1.8853x over previous
#include <cuda_runtime.h>
#include <math.h>
#include <stdint.h>

// ---- problem constants ----
#define VV 100000
#define EE 400000
#define GG 200
#define NFEAT 74
#define NEFEAT 12
#define NGMAX 8192

// ---- scratch ----
__device__ float    g_hv [VV * GG];
__device__ float    g_he1[EE * GG];
__device__ float    g_c  [VV * GG];
__device__ float    g_hvp[VV * GG];
__device__ float    g_gi [VV * 3 * GG];
__device__ float    g_gh [VV * 3 * GG];
__device__ float    g_mask[VV];
__device__ float    g_d0[VV];
__device__ float    g_d1[VV];
__device__ unsigned g_nmax[VV];
__device__ float    g_nsum[VV];
__device__ float    g_logit[EE];
__device__ float    g_att[EE];
__device__ float    g_gsum[NGMAX];

// ---- helpers ----
__device__ __forceinline__ float lreluf(float x) { return x > 0.f ? x : 0.01f * x; }
__device__ __forceinline__ float sigmoidf_(float x) { return 1.f / (1.f + expf(-x)); }
__device__ __forceinline__ unsigned fenc(float f) {
    unsigned b = __float_as_uint(f);
    return (b & 0x80000000u) ? ~b : (b | 0x80000000u);
}
__device__ __forceinline__ float fdec(unsigned u) {
    unsigned b = (u & 0x80000000u) ? (u & 0x7fffffffu) : ~u;
    return __uint_as_float(b);
}
__device__ __forceinline__ float warp_sum(float v) {
    #pragma unroll
    for (int o = 16; o; o >>= 1) v += __shfl_down_sync(0xffffffffu, v, o);
    return v;
}
__device__ __forceinline__ uint32_t to_tf32(float v) {
    uint32_t u;
    asm("cvt.rna.tf32.f32 %0, %1;" : "=r"(u) : "f"(v));
    return u;
}

// ---- fills ----
__global__ void fill_f_kernel(float* p, float v, int n) {
    int i = blockIdx.x * blockDim.x + threadIdx.x;
    if (i < n) p[i] = v;
}
__global__ void fill_u_kernel(unsigned* p, unsigned v, int n) {
    int i = blockIdx.x * blockDim.x + threadIdx.x;
    if (i < n) p[i] = v;
}

// ---- mask ----
__global__ void mask_kernel(const float* __restrict__ nf, float* __restrict__ mask, int V) {
    int v = blockIdx.x * blockDim.x + threadIdx.x;
    if (v >= V) return;
    const float* r = nf + (long)v * NFEAT;
    float s = r[NFEAT - 4] + r[NFEAT - 3] + r[NFEAT - 2] + r[NFEAT - 1];
    float m = s * (1.f - r[0]);
    mask[v] = 1.f / m - 1.f;
}

// ============================================================
// TF32 tensor-core GEMM: C(MxN) = op(A)(MxK) @ B(KxN) + bias
// AM: 0=direct, 1=elu(direct), 2=concat [node_feats[src[row]] | edge_feats[row]]
// EPI: 0=store, 1=lrelu store, 2=(acc+bias)*ascale[row] atomicAdd C[dstidx[row]*N+col]
// Tile: BM=128, BN=128, BK=16. 8 warps, each 64x32 (4x4 grid of m16n8k8).
// ============================================================
#define BM 128
#define BN 128
#define BK 16
#define SA 20    // A smem row stride (floats): banks (20*g+t)%32 all distinct
#define SB 136   // B smem row stride: banks (8*r+g)%32 all distinct

template<int AM, int EPI>
__global__ __launch_bounds__(256, 2)
void mma_gemm_kernel(const float* __restrict__ A, int lda,
                     const float* __restrict__ B,
                     const float* __restrict__ bias,
                     float* __restrict__ C,
                     int M, int N, int K,
                     const float* __restrict__ nodef, const float* __restrict__ edgef,
                     const int* __restrict__ src,
                     const float* __restrict__ ascale, const int* __restrict__ dstidx)
{
    __shared__ uint32_t As[2][BM * SA];
    __shared__ uint32_t Bs[2][BK * SB];

    const int tid = threadIdx.x;
    const int row0 = blockIdx.y * BM;
    const int col0 = blockIdx.x * BN;
    const int warp = tid >> 5, lane = tid & 31;
    const int gq = lane >> 2, tq = lane & 3;          // quad row / quad lane
    const int wm = (warp & 1) * 64;
    const int wn = (warp >> 1) * 32;
    const int nk = (K + BK - 1) / BK;

    float acc[4][4][4];
    #pragma unroll
    for (int a = 0; a < 4; a++)
        #pragma unroll
        for (int b = 0; b < 4; b++)
            #pragma unroll
            for (int c_ = 0; c_ < 4; c_++) acc[a][b][c_] = 0.f;

    float ra[8], rb[8];

    // --- staging loads (gmem -> regs) ---
    auto loadA = [&](int k0) {
        #pragma unroll
        for (int i = 0; i < 8; i++) {
            int idx = i * 256 + tid;
            int r = idx >> 4, kk = idx & 15;
            int gr = row0 + r, gk = k0 + kk;
            float v = 0.f;
            if (gr < M && gk < K) {
                if (AM == 2) {
                    if (gk < NFEAT) { int s = src[gr]; v = nodef[(long)s * NFEAT + gk]; }
                    else            { v = edgef[(long)gr * NEFEAT + (gk - NFEAT)]; }
                } else {
                    v = A[(long)gr * lda + gk];
                    if (AM == 1) v = v > 0.f ? v : expm1f(v);
                }
            }
            ra[i] = v;
        }
    };
    auto loadB = [&](int k0) {
        #pragma unroll
        for (int i = 0; i < 8; i++) {
            int idx = i * 256 + tid;
            int kk = idx >> 7, n = idx & 127;
            int gk = k0 + kk, gn = col0 + n;
            rb[i] = (gk < K && gn < N) ? B[(long)gk * N + gn] : 0.f;
        }
    };
    auto storeA = [&](int buf) {
        #pragma unroll
        for (int i = 0; i < 8; i++) {
            int idx = i * 256 + tid;
            int r = idx >> 4, kk = idx & 15;
            As[buf][r * SA + kk] = to_tf32(ra[i]);
        }
    };
    auto storeB = [&](int buf) {
        #pragma unroll
        for (int i = 0; i < 8; i++) {
            int idx = i * 256 + tid;
            int kk = idx >> 7, n = idx & 127;
            Bs[buf][kk * SB + n] = to_tf32(rb[i]);
        }
    };
    auto compute = [&](int buf) {
        #pragma unroll
        for (int ks = 0; ks < 2; ks++) {
            uint32_t af[4][4], bf[4][2];
            #pragma unroll
            for (int mt = 0; mt < 4; mt++) {
                int r = wm + mt * 16 + gq;
                int kb = ks * 8 + tq;
                af[mt][0] = As[buf][(r    ) * SA + kb    ];
                af[mt][1] = As[buf][(r + 8) * SA + kb    ];
                af[mt][2] = As[buf][(r    ) * SA + kb + 4];
                af[mt][3] = As[buf][(r + 8) * SA + kb + 4];
            }
            #pragma unroll
            for (int nt = 0; nt < 4; nt++) {
                int n = wn + nt * 8 + gq;
                int kb = ks * 8 + tq;
                bf[nt][0] = Bs[buf][(kb    ) * SB + n];
                bf[nt][1] = Bs[buf][(kb + 4) * SB + n];
            }
            #pragma unroll
            for (int mt = 0; mt < 4; mt++)
                #pragma unroll
                for (int nt = 0; nt < 4; nt++) {
                    asm volatile(
                        "mma.sync.aligned.m16n8k8.row.col.f32.tf32.tf32.f32 "
                        "{%0,%1,%2,%3},{%4,%5,%6,%7},{%8,%9},{%0,%1,%2,%3};"
                        : "+f"(acc[mt][nt][0]), "+f"(acc[mt][nt][1]),
                          "+f"(acc[mt][nt][2]), "+f"(acc[mt][nt][3])
                        : "r"(af[mt][0]), "r"(af[mt][1]), "r"(af[mt][2]), "r"(af[mt][3]),
                          "r"(bf[nt][0]), "r"(bf[nt][1]));
                }
        }
    };

    // --- pipelined main loop ---
    loadA(0); loadB(0);
    storeA(0); storeB(0);
    __syncthreads();
    for (int kt = 0; kt < nk; kt++) {
        int buf = kt & 1;
        if (kt + 1 < nk) { loadA((kt + 1) * BK); loadB((kt + 1) * BK); }
        compute(buf);
        if (kt + 1 < nk) {
            __syncthreads();
            storeA(buf ^ 1); storeB(buf ^ 1);
            __syncthreads();
        }
    }

    // --- epilogue ---
    #pragma unroll
    for (int mt = 0; mt < 4; mt++) {
        int r0 = row0 + wm + mt * 16 + gq;
        int r1 = r0 + 8;
        float as0 = 0.f, as1 = 0.f; int dd0 = 0, dd1 = 0;
        if (EPI == 2) {
            if (r0 < M) { as0 = ascale[r0]; dd0 = dstidx[r0]; }
            if (r1 < M) { as1 = ascale[r1]; dd1 = dstidx[r1]; }
        }
        #pragma unroll
        for (int nt = 0; nt < 4; nt++) {
            int cb = col0 + wn + nt * 8 + tq * 2;
            #pragma unroll
            for (int j = 0; j < 2; j++) {
                int cn = cb + j;
                if (cn >= N) continue;
                float bv = bias[cn];
                if (r0 < M) {
                    float v = acc[mt][nt][j] + bv;
                    if (EPI == 1) v = lreluf(v);
                    if (EPI == 2) atomicAdd(&C[(long)dd0 * N + cn], v * as0);
                    else          C[(long)r0 * N + cn] = v;
                }
                if (r1 < M) {
                    float v = acc[mt][nt][2 + j] + bv;
                    if (EPI == 1) v = lreluf(v);
                    if (EPI == 2) atomicAdd(&C[(long)dd1 * N + cn], v * as1);
                    else          C[(long)r1 * N + cn] = v;
                }
            }
        }
    }
}

// ---- per-node dot(s) ----
__global__ void node_dots_kernel(const float* __restrict__ X,
                                 const float* __restrict__ w0, const float* __restrict__ w1,
                                 float* __restrict__ out0, float* __restrict__ out1, int V)
{
    int warp = (blockIdx.x * blockDim.x + threadIdx.x) >> 5;
    int lane = threadIdx.x & 31;
    if (warp >= V) return;
    const float* x = X + (long)warp * GG;
    float s0 = 0.f, s1 = 0.f;
    for (int j = lane; j < GG; j += 32) {
        float xv = x[j];
        s0 += xv * w0[j];
        if (w1) s1 += xv * w1[j];
    }
    s0 = warp_sum(s0);
    if (w1) s1 = warp_sum(s1);
    if (lane == 0) {
        out0[warp] = s0;
        if (w1) out1[warp] = s1;
    }
}

// ---- context edge logit ----
__global__ void edge_ctx_logit_kernel(const float* __restrict__ he1,
                                      const float* __restrict__ w, const float* __restrict__ b,
                                      const float* __restrict__ d0, const int* __restrict__ dst,
                                      float* __restrict__ logit, int E)
{
    int warp = (blockIdx.x * blockDim.x + threadIdx.x) >> 5;
    int lane = threadIdx.x & 31;
    if (warp >= E) return;
    const float* x = he1 + (long)warp * GG;
    float s = 0.f;
    for (int j = lane; j < GG; j += 32) s += x[j] * w[j];
    s = warp_sum(s);
    if (lane == 0) logit[warp] = lreluf(d0[dst[warp]] + s + b[0]);
}

// ---- layer edge logit ----
__global__ void edge_layer_logit_kernel(const float* __restrict__ d0, const float* __restrict__ d1,
                                        const int* __restrict__ src, const int* __restrict__ dst,
                                        const float* __restrict__ b, float* __restrict__ logit, int E)
{
    int e = blockIdx.x * blockDim.x + threadIdx.x;
    if (e >= E) return;
    logit[e] = lreluf(d0[dst[e]] + d1[src[e]] + b[0]);
}

// ---- edge softmax (atomics) ----
__global__ void smax_max_kernel(const float* __restrict__ logit, const int* __restrict__ dst,
                                unsigned* __restrict__ nmax, int E)
{
    int e = blockIdx.x * blockDim.x + threadIdx.x;
    if (e >= E) return;
    atomicMax(&nmax[dst[e]], fenc(logit[e]));
}
__global__ void smax_expsum_kernel(const float* __restrict__ logit, const int* __restrict__ dst,
                                   const unsigned* __restrict__ nmax, float* __restrict__ nsum,
                                   float* __restrict__ a, int E)
{
    int e = blockIdx.x * blockDim.x + threadIdx.x;
    if (e >= E) return;
    int d = dst[e];
    float v = expf(logit[e] - fdec(nmax[d]));
    a[e] = v;
    atomicAdd(&nsum[d], v);
}
__global__ void smax_norm_kernel(const int* __restrict__ dst, const float* __restrict__ nsum,
                                 float* __restrict__ a, int E)
{
    int e = blockIdx.x * blockDim.x + threadIdx.x;
    if (e >= E) return;
    a[e] /= nsum[dst[e]];
}

// ---- scatter c[dst] += a[e]*hvp[src] ----
__global__ void scatter_c_kernel(const float* __restrict__ hvp, const float* __restrict__ a,
                                 const int* __restrict__ src, const int* __restrict__ dst,
                                 float* __restrict__ c, int E)
{
    int warp = (blockIdx.x * blockDim.x + threadIdx.x) >> 5;
    int lane = threadIdx.x & 31;
    if (warp >= E) return;
    float av = a[warp];
    const float* hs = hvp + (long)src[warp] * GG;
    float* cd = c + (long)dst[warp] * GG;
    for (int j = lane; j < GG; j += 32) atomicAdd(&cd[j], av * hs[j]);
}

// ---- GRU gates ----
__global__ void gru_gates_kernel(const float* __restrict__ gi, const float* __restrict__ gh,
                                 float* __restrict__ h, int V)
{
    int idx = blockIdx.x * blockDim.x + threadIdx.x;
    if (idx >= V * GG) return;
    int v = idx / GG, j = idx - v * GG;
    const float* gvi = gi + (long)v * 3 * GG;
    const float* gvh = gh + (long)v * 3 * GG;
    float r = sigmoidf_(gvi[j]          + gvh[j]);
    float z = sigmoidf_(gvi[j + GG]     + gvh[j + GG]);
    float n = tanhf   (gvi[j + 2 * GG] + r * gvh[j + 2 * GG]);
    float hv = h[idx];
    float o = (1.f - z) * n + z * hv;
    h[idx] = o > 0.f ? o : 0.f;
}

// ---- readout ----
__global__ void pred_kernel(const float* __restrict__ nf, const float* __restrict__ predW,
                            const float* __restrict__ predb, const float* __restrict__ mask,
                            const int* __restrict__ gids, float* __restrict__ out_atom,
                            float* __restrict__ gsum, int V)
{
    int warp = (blockIdx.x * blockDim.x + threadIdx.x) >> 5;
    int lane = threadIdx.x & 31;
    if (warp >= V) return;
    const float* x = nf + (long)warp * GG;
    float s = 0.f;
    for (int j = lane; j < GG; j += 32) s += x[j] * predW[j];
    s = warp_sum(s);
    if (lane == 0) {
        float ap = s + predb[0] + mask[warp];
        out_atom[warp] = ap;
        atomicAdd(&gsum[gids[warp]], exp10f(-ap));
    }
}
__global__ void final_kernel(const float* __restrict__ gsum, float* __restrict__ out, int NG) {
    int g = blockIdx.x * blockDim.x + threadIdx.x;
    if (g >= NG) return;
    out[g] = -log10f(gsum[g]);
}

// ---- host ----
static inline int cdiv(int a, int b) { return (a + b - 1) / b; }

extern "C" void kernel_launch(void* const* d_in, const int* in_sizes, int n_in,
                              void* d_out, int out_size)
{
    const float* node_feats = (const float*)d_in[0];
    const float* edge_feats = (const float*)d_in[1];
    const float* pn_W  = (const float*)d_in[2];
    const float* pn_b  = (const float*)d_in[3];
    const float* pe1_W = (const float*)d_in[4];
    const float* pe1_b = (const float*)d_in[5];
    const float* pe2_W = (const float*)d_in[6];
    const float* pe2_b = (const float*)d_in[7];
    const float* et_W  = (const float*)d_in[8];
    const float* et_b  = (const float*)d_in[9];
    const float* gru0_Wih = (const float*)d_in[10];
    const float* gru0_Whh = (const float*)d_in[11];
    const float* gru0_bih = (const float*)d_in[12];
    const float* gru0_bhh = (const float*)d_in[13];
    const float* gnn_pe_W = (const float*)d_in[14];
    const float* gnn_pe_b = (const float*)d_in[15];
    const float* gnn_pn_W = (const float*)d_in[16];
    const float* gnn_pn_b = (const float*)d_in[17];
    const float* gnn_gru_Wih = (const float*)d_in[18];
    const float* gnn_gru_Whh = (const float*)d_in[19];
    const float* gnn_gru_bih = (const float*)d_in[20];
    const float* gnn_gru_bhh = (const float*)d_in[21];
    const float* pred_W = (const float*)d_in[22];
    const float* pred_b = (const float*)d_in[23];
    const int* srci = (const int*)d_in[24];
    const int* dsti = (const int*)d_in[25];
    const int* gids = (const int*)d_in[26];

    int V = in_sizes[0] / NFEAT;
    int E = in_sizes[24];
    int NG = out_size - V;
    float* out = (float*)d_out;
    int L = in_sizes[15];

    float *hv, *he1, *c, *hvp, *gi, *gh, *maskp, *d0, *d1, *nsum, *logit, *att, *gsum;
    unsigned* nmax;
    cudaGetSymbolAddress((void**)&hv,   g_hv);
    cudaGetSymbolAddress((void**)&he1,  g_he1);
    cudaGetSymbolAddress((void**)&c,    g_c);
    cudaGetSymbolAddress((void**)&hvp,  g_hvp);
    cudaGetSymbolAddress((void**)&gi,   g_gi);
    cudaGetSymbolAddress((void**)&gh,   g_gh);
    cudaGetSymbolAddress((void**)&maskp,g_mask);
    cudaGetSymbolAddress((void**)&d0,   g_d0);
    cudaGetSymbolAddress((void**)&d1,   g_d1);
    cudaGetSymbolAddress((void**)&nmax, g_nmax);
    cudaGetSymbolAddress((void**)&nsum, g_nsum);
    cudaGetSymbolAddress((void**)&logit,g_logit);
    cudaGetSymbolAddress((void**)&att,  g_att);
    cudaGetSymbolAddress((void**)&gsum, g_gsum);

    dim3 blk(256);

    mask_kernel<<<cdiv(V, 256), blk>>>(node_feats, maskp, V);

    // hv_new = lrelu(node_feats @ pn_W + pn_b)
    {
        dim3 g(cdiv(GG, BN), cdiv(V, BM));
        mma_gemm_kernel<0, 1><<<g, blk>>>(node_feats, NFEAT, pn_W, pn_b, hv,
                                          V, GG, NFEAT, nullptr, nullptr, nullptr, nullptr, nullptr);
    }
    // he1 = lrelu(concat(node_feats[src], edge_feats) @ pe1_W + pe1_b)
    {
        dim3 g(cdiv(GG, BN), cdiv(E, BM));
        mma_gemm_kernel<2, 1><<<g, blk>>>(nullptr, 0, pe1_W, pe1_b, he1,
                                          E, GG, NFEAT + NEFEAT, node_feats, edge_feats, srci,
                                          nullptr, nullptr);
    }
    node_dots_kernel<<<cdiv(V, 8), blk>>>(hv, pe2_W, nullptr, d0, nullptr, V);
    edge_ctx_logit_kernel<<<cdiv(E, 8), blk>>>(he1, pe2_W + GG, pe2_b, d0, dsti, logit, E);
    fill_u_kernel<<<cdiv(V, 256), blk>>>(nmax, 0u, V);
    fill_f_kernel<<<cdiv(V, 256), blk>>>(nsum, 0.f, V);
    smax_max_kernel<<<cdiv(E, 256), blk>>>(logit, dsti, nmax, E);
    smax_expsum_kernel<<<cdiv(E, 256), blk>>>(logit, dsti, nmax, nsum, att, E);
    smax_norm_kernel<<<cdiv(E, 256), blk>>>(dsti, nsum, att, E);
    // c = segment_sum(a * (he1 @ et_W + et_b), dst)
    fill_f_kernel<<<cdiv(V * GG, 256), blk>>>(c, 0.f, V * GG);
    {
        dim3 g(cdiv(GG, BN), cdiv(E, BM));
        mma_gemm_kernel<0, 2><<<g, blk>>>(he1, GG, et_W, et_b, c,
                                          E, GG, GG, nullptr, nullptr, nullptr, att, dsti);
    }
    // GRU0
    {
        dim3 g(cdiv(3 * GG, BN), cdiv(V, BM));
        mma_gemm_kernel<1, 0><<<g, blk>>>(c, GG, gru0_Wih, gru0_bih, gi,
                                          V, 3 * GG, GG, nullptr, nullptr, nullptr, nullptr, nullptr);
        mma_gemm_kernel<0, 0><<<g, blk>>>(hv, GG, gru0_Whh, gru0_bhh, gh,
                                          V, 3 * GG, GG, nullptr, nullptr, nullptr, nullptr, nullptr);
    }
    gru_gates_kernel<<<cdiv(V * GG, 256), blk>>>(gi, gh, hv, V);

    for (int l = 0; l < L; l++) {
        node_dots_kernel<<<cdiv(V, 8), blk>>>(hv, gnn_pe_W + (long)l * 2 * GG,
                                              gnn_pe_W + (long)l * 2 * GG + GG, d0, d1, V);
        edge_layer_logit_kernel<<<cdiv(E, 256), blk>>>(d0, d1, srci, dsti, gnn_pe_b + l, logit, E);
        fill_u_kernel<<<cdiv(V, 256), blk>>>(nmax, 0u, V);
        fill_f_kernel<<<cdiv(V, 256), blk>>>(nsum, 0.f, V);
        smax_max_kernel<<<cdiv(E, 256), blk>>>(logit, dsti, nmax, E);
        smax_expsum_kernel<<<cdiv(E, 256), blk>>>(logit, dsti, nmax, nsum, att, E);
        smax_norm_kernel<<<cdiv(E, 256), blk>>>(dsti, nsum, att, E);
        {
            dim3 g(cdiv(GG, BN), cdiv(V, BM));
            mma_gemm_kernel<0, 0><<<g, blk>>>(hv, GG, gnn_pn_W + (long)l * GG * GG,
                                              gnn_pn_b + (long)l * GG, hvp,
                                              V, GG, GG, nullptr, nullptr, nullptr, nullptr, nullptr);
        }
        fill_f_kernel<<<cdiv(V * GG, 256), blk>>>(c, 0.f, V * GG);
        scatter_c_kernel<<<cdiv(E, 8), blk>>>(hvp, att, srci, dsti, c, E);
        {
            dim3 g(cdiv(3 * GG, BN), cdiv(V, BM));
            mma_gemm_kernel<1, 0><<<g, blk>>>(c, GG, gnn_gru_Wih + (long)l * GG * 3 * GG,
                                              gnn_gru_bih + (long)l * 3 * GG, gi,
                                              V, 3 * GG, GG, nullptr, nullptr, nullptr, nullptr, nullptr);
            mma_gemm_kernel<0, 0><<<g, blk>>>(hv, GG, gnn_gru_Whh + (long)l * GG * 3 * GG,
                                              gnn_gru_bhh + (long)l * 3 * GG, gh,
                                              V, 3 * GG, GG, nullptr, nullptr, nullptr, nullptr, nullptr);
        }
        gru_gates_kernel<<<cdiv(V * GG, 256), blk>>>(gi, gh, hv, V);
    }

    fill_f_kernel<<<cdiv(NG, 256), blk>>>(gsum, 0.f, NG);
    pred_kernel<<<cdiv(V, 8), blk>>>(hv, pred_W, pred_b, maskp, gids, out + NG, gsum, V);
    final_kernel<<<cdiv(NG, 256), blk>>>(gsum, out, NG);
}

// round 3
// speedup vs baseline: 2.3851x; 1.2651x over previous
#include <cuda_runtime.h>
#include <cuda_bf16.h>
#include <math.h>
#include <stdint.h>

// ---- problem constants ----
#define VV 100000
#define EE 400000
#define GG 200
#define NFEAT 74
#define NEFEAT 12
#define NGMAX 8192

// ---- scratch ----
__device__ float    g_hv [VV * GG];
__device__ float    g_he1[EE * GG];
__device__ float    g_c  [VV * GG];
__device__ float    g_hvp[VV * GG];
__device__ float    g_gi [VV * 3 * GG];
__device__ float    g_gh [VV * 3 * GG];
__device__ float    g_mask[VV];
__device__ float    g_d0[VV];
__device__ float    g_d1[VV];
__device__ unsigned g_nmax[VV];
__device__ float    g_nsum[VV];
__device__ float    g_logit[EE];
__device__ float    g_att[EE];
__device__ float    g_gsum[NGMAX];

// ---- helpers ----
__device__ __forceinline__ float lreluf(float x) { return x > 0.f ? x : 0.01f * x; }
__device__ __forceinline__ float sigmoidf_(float x) { return 1.f / (1.f + expf(-x)); }
__device__ __forceinline__ unsigned fenc(float f) {
    unsigned b = __float_as_uint(f);
    return (b & 0x80000000u) ? ~b : (b | 0x80000000u);
}
__device__ __forceinline__ float fdec(unsigned u) {
    unsigned b = (u & 0x80000000u) ? (u & 0x7fffffffu) : ~u;
    return __uint_as_float(b);
}
__device__ __forceinline__ float warp_sum(float v) {
    #pragma unroll
    for (int o = 16; o; o >>= 1) v += __shfl_down_sync(0xffffffffu, v, o);
    return v;
}
__device__ __forceinline__ uint32_t packbf(float lo, float hi) {
    __nv_bfloat162 p = __floats2bfloat162_rn(lo, hi);
    return *reinterpret_cast<uint32_t*>(&p);
}

// ---- fills ----
__global__ void fill_f_kernel(float* p, float v, int n) {
    int i = blockIdx.x * blockDim.x + threadIdx.x;
    if (i < n) p[i] = v;
}
__global__ void fill_u_kernel(unsigned* p, unsigned v, int n) {
    int i = blockIdx.x * blockDim.x + threadIdx.x;
    if (i < n) p[i] = v;
}

// ---- mask ----
__global__ void mask_kernel(const float* __restrict__ nf, float* __restrict__ mask, int V) {
    int v = blockIdx.x * blockDim.x + threadIdx.x;
    if (v >= V) return;
    const float* r = nf + (long)v * NFEAT;
    float s = r[NFEAT - 4] + r[NFEAT - 3] + r[NFEAT - 2] + r[NFEAT - 1];
    float m = s * (1.f - r[0]);
    mask[v] = 1.f / m - 1.f;
}

// ============================================================
// BF16 tensor-core GEMM (mma.m16n8k16, fp32 accum)
// C(MxN) = op(A)(MxK) @ B(KxN) + bias
// AM: 0=direct, 1=elu(direct), 2=concat [node_feats[src[row]] | edge_feats[row]]
// EPI: 0=store, 1=lrelu store, 2=(acc+bias)*ascale[row] atomicAdd C[dstidx[row]*N+col]
// Tile: BM=128, BN=128, BK=32. 8 warps, each 64x32.
// Requires K even (74/86/200 all even).
// ============================================================
#define BM 128
#define BN 128
#define BK 32
#define SA 20    // A row stride in u32 (16 used + 4 pad): read banks (20g+t) distinct
#define SB2 20   // B row stride in u32 (transposed [n][k2] layout)

template<int AM, int EPI>
__global__ __launch_bounds__(256, 2)
void mma_gemm_kernel(const float* __restrict__ A, int lda,
                     const float* __restrict__ B,
                     const float* __restrict__ bias,
                     float* __restrict__ C,
                     int M, int N, int K,
                     const float* __restrict__ nodef, const float* __restrict__ edgef,
                     const int* __restrict__ src,
                     const float* __restrict__ ascale, const int* __restrict__ dstidx)
{
    __shared__ uint32_t As[2][BM * SA];   // [row][k2] bf16x2 pairs along k
    __shared__ uint32_t Bs[2][BN * SB2];  // [col][k2] bf16x2 pairs along k

    const int tid = threadIdx.x;
    const int row0 = blockIdx.y * BM;
    const int col0 = blockIdx.x * BN;
    const int warp = tid >> 5, lane = tid & 31;
    const int gq = lane >> 2, tq = lane & 3;
    const int wm = (warp & 1) * 64;
    const int wn = (warp >> 1) * 32;
    const int nk = (K + BK - 1) / BK;

    float acc[4][4][4];
    #pragma unroll
    for (int a = 0; a < 4; a++)
        #pragma unroll
        for (int b = 0; b < 4; b++)
            #pragma unroll
            for (int c_ = 0; c_ < 4; c_++) acc[a][b][c_] = 0.f;

    uint32_t ra[8], rb[8];

    auto loadA = [&](int k0) {
        #pragma unroll
        for (int i = 0; i < 8; i++) {
            int e = i * 256 + tid;
            int r = e >> 4, k2 = e & 15;
            int gr = row0 + r, gk = k0 + 2 * k2;
            float v0 = 0.f, v1 = 0.f;
            if (gr < M && gk < K) {       // K even -> gk+1 < K too
                if (AM == 2) {
                    if (gk < NFEAT) {
                        int s = src[gr];
                        const float* p = &nodef[(long)s * NFEAT + gk];
                        v0 = p[0]; v1 = p[1];
                    } else {
                        const float* p = &edgef[(long)gr * NEFEAT + (gk - NFEAT)];
                        v0 = p[0]; v1 = p[1];
                    }
                } else {
                    const float2 p = *(const float2*)&A[(long)gr * lda + gk];
                    v0 = p.x; v1 = p.y;
                    if (AM == 1) {
                        v0 = v0 > 0.f ? v0 : expm1f(v0);
                        v1 = v1 > 0.f ? v1 : expm1f(v1);
                    }
                }
            }
            ra[i] = packbf(v0, v1);
        }
    };
    auto loadB = [&](int k0) {
        #pragma unroll
        for (int i = 0; i < 8; i++) {
            int e = i * 256 + tid;
            int k2 = e >> 7, n = e & 127;
            int gk = k0 + 2 * k2, gn = col0 + n;
            float v0 = 0.f, v1 = 0.f;
            if (gk < K && gn < N) {
                v0 = B[(long)gk * N + gn];
                v1 = B[(long)(gk + 1) * N + gn];
            }
            rb[i] = packbf(v0, v1);
        }
    };
    auto storeA = [&](int buf) {
        #pragma unroll
        for (int i = 0; i < 8; i++) {
            int e = i * 256 + tid;
            int r = e >> 4, k2 = e & 15;
            As[buf][r * SA + k2] = ra[i];
        }
    };
    auto storeB = [&](int buf) {
        #pragma unroll
        for (int i = 0; i < 8; i++) {
            int e = i * 256 + tid;
            int k2 = e >> 7, n = e & 127;
            Bs[buf][n * SB2 + k2] = rb[i];
        }
    };
    auto compute = [&](int buf) {
        #pragma unroll
        for (int ks = 0; ks < 2; ks++) {
            uint32_t af[4][4], bf[4][2];
            #pragma unroll
            for (int mt = 0; mt < 4; mt++) {
                int r = wm + mt * 16 + gq;
                int kb = ks * 8 + tq;
                af[mt][0] = As[buf][(r    ) * SA + kb    ];
                af[mt][1] = As[buf][(r + 8) * SA + kb    ];
                af[mt][2] = As[buf][(r    ) * SA + kb + 4];
                af[mt][3] = As[buf][(r + 8) * SA + kb + 4];
            }
            #pragma unroll
            for (int nt = 0; nt < 4; nt++) {
                int n = wn + nt * 8 + gq;
                int kb = ks * 8 + tq;
                bf[nt][0] = Bs[buf][n * SB2 + kb    ];
                bf[nt][1] = Bs[buf][n * SB2 + kb + 4];
            }
            #pragma unroll
            for (int mt = 0; mt < 4; mt++)
                #pragma unroll
                for (int nt = 0; nt < 4; nt++) {
                    asm volatile(
                        "mma.sync.aligned.m16n8k16.row.col.f32.bf16.bf16.f32 "
                        "{%0,%1,%2,%3},{%4,%5,%6,%7},{%8,%9},{%0,%1,%2,%3};"
                        : "+f"(acc[mt][nt][0]), "+f"(acc[mt][nt][1]),
                          "+f"(acc[mt][nt][2]), "+f"(acc[mt][nt][3])
                        : "r"(af[mt][0]), "r"(af[mt][1]), "r"(af[mt][2]), "r"(af[mt][3]),
                          "r"(bf[nt][0]), "r"(bf[nt][1]));
                }
        }
    };

    loadA(0); loadB(0);
    storeA(0); storeB(0);
    __syncthreads();
    for (int kt = 0; kt < nk; kt++) {
        int buf = kt & 1;
        if (kt + 1 < nk) { loadA((kt + 1) * BK); loadB((kt + 1) * BK); }
        compute(buf);
        if (kt + 1 < nk) {
            __syncthreads();
            storeA(buf ^ 1); storeB(buf ^ 1);
            __syncthreads();
        }
    }

    #pragma unroll
    for (int mt = 0; mt < 4; mt++) {
        int r0 = row0 + wm + mt * 16 + gq;
        int r1 = r0 + 8;
        float as0 = 0.f, as1 = 0.f; int dd0 = 0, dd1 = 0;
        if (EPI == 2) {
            if (r0 < M) { as0 = ascale[r0]; dd0 = dstidx[r0]; }
            if (r1 < M) { as1 = ascale[r1]; dd1 = dstidx[r1]; }
        }
        #pragma unroll
        for (int nt = 0; nt < 4; nt++) {
            int cb = col0 + wn + nt * 8 + tq * 2;
            #pragma unroll
            for (int j = 0; j < 2; j++) {
                int cn = cb + j;
                if (cn >= N) continue;
                float bv = bias[cn];
                if (r0 < M) {
                    float v = acc[mt][nt][j] + bv;
                    if (EPI == 1) v = lreluf(v);
                    if (EPI == 2) atomicAdd(&C[(long)dd0 * N + cn], v * as0);
                    else          C[(long)r0 * N + cn] = v;
                }
                if (r1 < M) {
                    float v = acc[mt][nt][2 + j] + bv;
                    if (EPI == 1) v = lreluf(v);
                    if (EPI == 2) atomicAdd(&C[(long)dd1 * N + cn], v * as1);
                    else          C[(long)r1 * N + cn] = v;
                }
            }
        }
    }
}

// ---- per-node dot(s) ----
__global__ void node_dots_kernel(const float* __restrict__ X,
                                 const float* __restrict__ w0, const float* __restrict__ w1,
                                 float* __restrict__ out0, float* __restrict__ out1, int V)
{
    int warp = (blockIdx.x * blockDim.x + threadIdx.x) >> 5;
    int lane = threadIdx.x & 31;
    if (warp >= V) return;
    const float* x = X + (long)warp * GG;
    float s0 = 0.f, s1 = 0.f;
    for (int j = lane; j < GG; j += 32) {
        float xv = x[j];
        s0 += xv * w0[j];
        if (w1) s1 += xv * w1[j];
    }
    s0 = warp_sum(s0);
    if (w1) s1 = warp_sum(s1);
    if (lane == 0) {
        out0[warp] = s0;
        if (w1) out1[warp] = s1;
    }
}

// ---- context edge logit ----
__global__ void edge_ctx_logit_kernel(const float* __restrict__ he1,
                                      const float* __restrict__ w, const float* __restrict__ b,
                                      const float* __restrict__ d0, const int* __restrict__ dst,
                                      float* __restrict__ logit, int E)
{
    int warp = (blockIdx.x * blockDim.x + threadIdx.x) >> 5;
    int lane = threadIdx.x & 31;
    if (warp >= E) return;
    const float* x = he1 + (long)warp * GG;
    float s = 0.f;
    for (int j = lane; j < GG; j += 32) s += x[j] * w[j];
    s = warp_sum(s);
    if (lane == 0) logit[warp] = lreluf(d0[dst[warp]] + s + b[0]);
}

// ---- layer edge logit ----
__global__ void edge_layer_logit_kernel(const float* __restrict__ d0, const float* __restrict__ d1,
                                        const int* __restrict__ src, const int* __restrict__ dst,
                                        const float* __restrict__ b, float* __restrict__ logit, int E)
{
    int e = blockIdx.x * blockDim.x + threadIdx.x;
    if (e >= E) return;
    logit[e] = lreluf(d0[dst[e]] + d1[src[e]] + b[0]);
}

// ---- edge softmax (atomics) ----
__global__ void smax_max_kernel(const float* __restrict__ logit, const int* __restrict__ dst,
                                unsigned* __restrict__ nmax, int E)
{
    int e = blockIdx.x * blockDim.x + threadIdx.x;
    if (e >= E) return;
    atomicMax(&nmax[dst[e]], fenc(logit[e]));
}
__global__ void smax_expsum_kernel(const float* __restrict__ logit, const int* __restrict__ dst,
                                   const unsigned* __restrict__ nmax, float* __restrict__ nsum,
                                   float* __restrict__ a, int E)
{
    int e = blockIdx.x * blockDim.x + threadIdx.x;
    if (e >= E) return;
    int d = dst[e];
    float v = expf(logit[e] - fdec(nmax[d]));
    a[e] = v;
    atomicAdd(&nsum[d], v);
}
__global__ void smax_norm_kernel(const int* __restrict__ dst, const float* __restrict__ nsum,
                                 float* __restrict__ a, int E)
{
    int e = blockIdx.x * blockDim.x + threadIdx.x;
    if (e >= E) return;
    a[e] /= nsum[dst[e]];
}

// ---- scatter c[dst] += a[e]*hvp[src] ----
__global__ void scatter_c_kernel(const float* __restrict__ hvp, const float* __restrict__ a,
                                 const int* __restrict__ src, const int* __restrict__ dst,
                                 float* __restrict__ c, int E)
{
    int warp = (blockIdx.x * blockDim.x + threadIdx.x) >> 5;
    int lane = threadIdx.x & 31;
    if (warp >= E) return;
    float av = a[warp];
    const float* hs = hvp + (long)src[warp] * GG;
    float* cd = c + (long)dst[warp] * GG;
    for (int j = lane; j < GG; j += 32) atomicAdd(&cd[j], av * hs[j]);
}

// ---- GRU gates ----
__global__ void gru_gates_kernel(const float* __restrict__ gi, const float* __restrict__ gh,
                                 float* __restrict__ h, int V)
{
    int idx = blockIdx.x * blockDim.x + threadIdx.x;
    if (idx >= V * GG) return;
    int v = idx / GG, j = idx - v * GG;
    const float* gvi = gi + (long)v * 3 * GG;
    const float* gvh = gh + (long)v * 3 * GG;
    float r = sigmoidf_(gvi[j]          + gvh[j]);
    float z = sigmoidf_(gvi[j + GG]     + gvh[j + GG]);
    float n = tanhf   (gvi[j + 2 * GG] + r * gvh[j + 2 * GG]);
    float hv = h[idx];
    float o = (1.f - z) * n + z * hv;
    h[idx] = o > 0.f ? o : 0.f;
}

// ---- readout ----
__global__ void pred_kernel(const float* __restrict__ nf, const float* __restrict__ predW,
                            const float* __restrict__ predb, const float* __restrict__ mask,
                            const int* __restrict__ gids, float* __restrict__ out_atom,
                            float* __restrict__ gsum, int V)
{
    int warp = (blockIdx.x * blockDim.x + threadIdx.x) >> 5;
    int lane = threadIdx.x & 31;
    if (warp >= V) return;
    const float* x = nf + (long)warp * GG;
    float s = 0.f;
    for (int j = lane; j < GG; j += 32) s += x[j] * predW[j];
    s = warp_sum(s);
    if (lane == 0) {
        float ap = s + predb[0] + mask[warp];
        out_atom[warp] = ap;
        atomicAdd(&gsum[gids[warp]], exp10f(-ap));
    }
}
__global__ void final_kernel(const float* __restrict__ gsum, float* __restrict__ out, int NG) {
    int g = blockIdx.x * blockDim.x + threadIdx.x;
    if (g >= NG) return;
    out[g] = -log10f(gsum[g]);
}

// ---- host ----
static inline int cdiv(int a, int b) { return (a + b - 1) / b; }

extern "C" void kernel_launch(void* const* d_in, const int* in_sizes, int n_in,
                              void* d_out, int out_size)
{
    const float* node_feats = (const float*)d_in[0];
    const float* edge_feats = (const float*)d_in[1];
    const float* pn_W  = (const float*)d_in[2];
    const float* pn_b  = (const float*)d_in[3];
    const float* pe1_W = (const float*)d_in[4];
    const float* pe1_b = (const float*)d_in[5];
    const float* pe2_W = (const float*)d_in[6];
    const float* pe2_b = (const float*)d_in[7];
    const float* et_W  = (const float*)d_in[8];
    const float* et_b  = (const float*)d_in[9];
    const float* gru0_Wih = (const float*)d_in[10];
    const float* gru0_Whh = (const float*)d_in[11];
    const float* gru0_bih = (const float*)d_in[12];
    const float* gru0_bhh = (const float*)d_in[13];
    const float* gnn_pe_W = (const float*)d_in[14];
    const float* gnn_pe_b = (const float*)d_in[15];
    const float* gnn_pn_W = (const float*)d_in[16];
    const float* gnn_pn_b = (const float*)d_in[17];
    const float* gnn_gru_Wih = (const float*)d_in[18];
    const float* gnn_gru_Whh = (const float*)d_in[19];
    const float* gnn_gru_bih = (const float*)d_in[20];
    const float* gnn_gru_bhh = (const float*)d_in[21];
    const float* pred_W = (const float*)d_in[22];
    const float* pred_b = (const float*)d_in[23];
    const int* srci = (const int*)d_in[24];
    const int* dsti = (const int*)d_in[25];
    const int* gids = (const int*)d_in[26];

    int V = in_sizes[0] / NFEAT;
    int E = in_sizes[24];
    int NG = out_size - V;
    float* out = (float*)d_out;
    int L = in_sizes[15];

    float *hv, *he1, *c, *hvp, *gi, *gh, *maskp, *d0, *d1, *nsum, *logit, *att, *gsum;
    unsigned* nmax;
    cudaGetSymbolAddress((void**)&hv,   g_hv);
    cudaGetSymbolAddress((void**)&he1,  g_he1);
    cudaGetSymbolAddress((void**)&c,    g_c);
    cudaGetSymbolAddress((void**)&hvp,  g_hvp);
    cudaGetSymbolAddress((void**)&gi,   g_gi);
    cudaGetSymbolAddress((void**)&gh,   g_gh);
    cudaGetSymbolAddress((void**)&maskp,g_mask);
    cudaGetSymbolAddress((void**)&d0,   g_d0);
    cudaGetSymbolAddress((void**)&d1,   g_d1);
    cudaGetSymbolAddress((void**)&nmax, g_nmax);
    cudaGetSymbolAddress((void**)&nsum, g_nsum);
    cudaGetSymbolAddress((void**)&logit,g_logit);
    cudaGetSymbolAddress((void**)&att,  g_att);
    cudaGetSymbolAddress((void**)&gsum, g_gsum);

    dim3 blk(256);

    mask_kernel<<<cdiv(V, 256), blk>>>(node_feats, maskp, V);

    // hv_new = lrelu(node_feats @ pn_W + pn_b)
    {
        dim3 g(cdiv(GG, BN), cdiv(V, BM));
        mma_gemm_kernel<0, 1><<<g, blk>>>(node_feats, NFEAT, pn_W, pn_b, hv,
                                          V, GG, NFEAT, nullptr, nullptr, nullptr, nullptr, nullptr);
    }
    // he1 = lrelu(concat(node_feats[src], edge_feats) @ pe1_W + pe1_b)
    {
        dim3 g(cdiv(GG, BN), cdiv(E, BM));
        mma_gemm_kernel<2, 1><<<g, blk>>>(nullptr, 0, pe1_W, pe1_b, he1,
                                          E, GG, NFEAT + NEFEAT, node_feats, edge_feats, srci,
                                          nullptr, nullptr);
    }
    node_dots_kernel<<<cdiv(V, 8), blk>>>(hv, pe2_W, nullptr, d0, nullptr, V);
    edge_ctx_logit_kernel<<<cdiv(E, 8), blk>>>(he1, pe2_W + GG, pe2_b, d0, dsti, logit, E);
    fill_u_kernel<<<cdiv(V, 256), blk>>>(nmax, 0u, V);
    fill_f_kernel<<<cdiv(V, 256), blk>>>(nsum, 0.f, V);
    smax_max_kernel<<<cdiv(E, 256), blk>>>(logit, dsti, nmax, E);
    smax_expsum_kernel<<<cdiv(E, 256), blk>>>(logit, dsti, nmax, nsum, att, E);
    smax_norm_kernel<<<cdiv(E, 256), blk>>>(dsti, nsum, att, E);
    // c = segment_sum(a * (he1 @ et_W + et_b), dst)
    fill_f_kernel<<<cdiv(V * GG, 256), blk>>>(c, 0.f, V * GG);
    {
        dim3 g(cdiv(GG, BN), cdiv(E, BM));
        mma_gemm_kernel<0, 2><<<g, blk>>>(he1, GG, et_W, et_b, c,
                                          E, GG, GG, nullptr, nullptr, nullptr, att, dsti);
    }
    // GRU0
    {
        dim3 g(cdiv(3 * GG, BN), cdiv(V, BM));
        mma_gemm_kernel<1, 0><<<g, blk>>>(c, GG, gru0_Wih, gru0_bih, gi,
                                          V, 3 * GG, GG, nullptr, nullptr, nullptr, nullptr, nullptr);
        mma_gemm_kernel<0, 0><<<g, blk>>>(hv, GG, gru0_Whh, gru0_bhh, gh,
                                          V, 3 * GG, GG, nullptr, nullptr, nullptr, nullptr, nullptr);
    }
    gru_gates_kernel<<<cdiv(V * GG, 256), blk>>>(gi, gh, hv, V);

    for (int l = 0; l < L; l++) {
        node_dots_kernel<<<cdiv(V, 8), blk>>>(hv, gnn_pe_W + (long)l * 2 * GG,
                                              gnn_pe_W + (long)l * 2 * GG + GG, d0, d1, V);
        edge_layer_logit_kernel<<<cdiv(E, 256), blk>>>(d0, d1, srci, dsti, gnn_pe_b + l, logit, E);
        fill_u_kernel<<<cdiv(V, 256), blk>>>(nmax, 0u, V);
        fill_f_kernel<<<cdiv(V, 256), blk>>>(nsum, 0.f, V);
        smax_max_kernel<<<cdiv(E, 256), blk>>>(logit, dsti, nmax, E);
        smax_expsum_kernel<<<cdiv(E, 256), blk>>>(logit, dsti, nmax, nsum, att, E);
        smax_norm_kernel<<<cdiv(E, 256), blk>>>(dsti, nsum, att, E);
        {
            dim3 g(cdiv(GG, BN), cdiv(V, BM));
            mma_gemm_kernel<0, 0><<<g, blk>>>(hv, GG, gnn_pn_W + (long)l * GG * GG,
                                              gnn_pn_b + (long)l * GG, hvp,
                                              V, GG, GG, nullptr, nullptr, nullptr, nullptr, nullptr);
        }
        fill_f_kernel<<<cdiv(V * GG, 256), blk>>>(c, 0.f, V * GG);
        scatter_c_kernel<<<cdiv(E, 8), blk>>>(hvp, att, srci, dsti, c, E);
        {
            dim3 g(cdiv(3 * GG, BN), cdiv(V, BM));
            mma_gemm_kernel<1, 0><<<g, blk>>>(c, GG, gnn_gru_Wih + (long)l * GG * 3 * GG,
                                              gnn_gru_bih + (long)l * 3 * GG, gi,
                                              V, 3 * GG, GG, nullptr, nullptr, nullptr, nullptr, nullptr);
            mma_gemm_kernel<0, 0><<<g, blk>>>(hv, GG, gnn_gru_Whh + (long)l * GG * 3 * GG,
                                              gnn_gru_bhh + (long)l * 3 * GG, gh,
                                              V, 3 * GG, GG, nullptr, nullptr, nullptr, nullptr, nullptr);
        }
        gru_gates_kernel<<<cdiv(V * GG, 256), blk>>>(gi, gh, hv, V);
    }

    fill_f_kernel<<<cdiv(NG, 256), blk>>>(gsum, 0.f, NG);
    pred_kernel<<<cdiv(V, 8), blk>>>(hv, pred_W, pred_b, maskp, gids, out + NG, gsum, V);
    final_kernel<<<cdiv(NG, 256), blk>>>(gsum, out, NG);
}

// round 4
// speedup vs baseline: 2.4467x; 1.0258x over previous
#include <cuda_runtime.h>
#include <cuda_bf16.h>
#include <math.h>
#include <stdint.h>

// ---- problem constants ----
#define VV 100000
#define EE 400000
#define GG 200
#define NFEAT 74
#define NEFEAT 12
#define NGMAX 8192

// ---- scratch ----
__device__ float    g_hv [VV * GG];
__device__ float    g_he1[EE * GG];
__device__ float    g_c  [VV * GG];
__device__ float    g_hvp[VV * GG];
__device__ float    g_gi [VV * 3 * GG];
__device__ float    g_gh [VV * 3 * GG];
__device__ float    g_mask[VV];
__device__ float    g_d0[VV];
__device__ float    g_d1[VV];
__device__ float    g_logit[EE];
__device__ float    g_att[EE];
__device__ float    g_gsum[NGMAX];
// CSR
__device__ int      g_rowptr[VV + 1];
__device__ int      g_cursor[VV];
__device__ int      g_csr[EE];

// ---- helpers ----
__device__ __forceinline__ float lreluf(float x) { return x > 0.f ? x : 0.01f * x; }
__device__ __forceinline__ float sigmoidf_(float x) { return 1.f / (1.f + expf(-x)); }
__device__ __forceinline__ float warp_sum(float v) {
    #pragma unroll
    for (int o = 16; o; o >>= 1) v += __shfl_down_sync(0xffffffffu, v, o);
    return v;
}
__device__ __forceinline__ float warp_allmax(float v) {
    #pragma unroll
    for (int o = 16; o; o >>= 1) v = fmaxf(v, __shfl_xor_sync(0xffffffffu, v, o));
    return v;
}
__device__ __forceinline__ float warp_allsum(float v) {
    #pragma unroll
    for (int o = 16; o; o >>= 1) v += __shfl_xor_sync(0xffffffffu, v, o);
    return v;
}
__device__ __forceinline__ uint32_t packbf(float lo, float hi) {
    __nv_bfloat162 p = __floats2bfloat162_rn(lo, hi);
    return *reinterpret_cast<uint32_t*>(&p);
}

// ---- fills ----
__global__ void fill_f_kernel(float* p, float v, int n) {
    int i = blockIdx.x * blockDim.x + threadIdx.x;
    if (i < n) p[i] = v;
}
__global__ void fill_i_kernel(int* p, int v, int n) {
    int i = blockIdx.x * blockDim.x + threadIdx.x;
    if (i < n) p[i] = v;
}

// ---- CSR build ----
__global__ void hist_kernel(const int* __restrict__ dst, int* __restrict__ rowptr, int E) {
    int e = blockIdx.x * blockDim.x + threadIdx.x;
    if (e < E) atomicAdd(&rowptr[dst[e] + 1], 1);
}
// single-block inclusive scan over n elements (n <= 1024*CHUNK)
__global__ void scan_kernel(int* __restrict__ p, int n) {
    __shared__ int tsum[1024];
    int tid = threadIdx.x;
    int chunk = (n + 1023) / 1024;
    int s0 = tid * chunk, s1 = min(s0 + chunk, n);
    int sum = 0;
    for (int i = s0; i < s1; i++) sum += p[i];
    tsum[tid] = sum;
    __syncthreads();
    // block exclusive scan of tsum
    int val = tsum[tid];
    #pragma unroll
    for (int o = 1; o < 1024; o <<= 1) {
        int other = (tid >= o) ? tsum[tid - o] : 0;
        __syncthreads();
        val += other;
        tsum[tid] = val;
        __syncthreads();
    }
    int offset = (tid > 0) ? tsum[tid - 1] : 0;
    int run = offset;
    for (int i = s0; i < s1; i++) {
        run += p[i];
        p[i] = run;
    }
}
__global__ void copy_i_kernel(const int* __restrict__ a, int* __restrict__ b, int n) {
    int i = blockIdx.x * blockDim.x + threadIdx.x;
    if (i < n) b[i] = a[i];
}
__global__ void csr_scatter_kernel(const int* __restrict__ dst, int* __restrict__ cursor,
                                   int* __restrict__ csr, int E) {
    int e = blockIdx.x * blockDim.x + threadIdx.x;
    if (e >= E) return;
    int pos = atomicAdd(&cursor[dst[e]], 1);
    csr[pos] = e;
}

// ---- mask ----
__global__ void mask_kernel(const float* __restrict__ nf, float* __restrict__ mask, int V) {
    int v = blockIdx.x * blockDim.x + threadIdx.x;
    if (v >= V) return;
    const float* r = nf + (long)v * NFEAT;
    float s = r[NFEAT - 4] + r[NFEAT - 3] + r[NFEAT - 2] + r[NFEAT - 1];
    float m = s * (1.f - r[0]);
    mask[v] = 1.f / m - 1.f;
}

// ============================================================
// BF16 tensor-core GEMM (mma.m16n8k16, fp32 accum)
// AM: 0=direct, 1=elu(direct), 2=concat [node_feats[src[row]] | edge_feats[row]]
// EPI: 0=store(+bias), 1=lrelu(+bias)
// ============================================================
#define BM 128
#define BN 128
#define BK 32
#define SA 20
#define SB2 20

template<int AM, int EPI>
__global__ __launch_bounds__(256, 2)
void mma_gemm_kernel(const float* __restrict__ A, int lda,
                     const float* __restrict__ B,
                     const float* __restrict__ bias,
                     float* C,
                     int M, int N, int K,
                     const float* __restrict__ nodef, const float* __restrict__ edgef,
                     const int* __restrict__ src)
{
    __shared__ uint32_t As[2][BM * SA];
    __shared__ uint32_t Bs[2][BN * SB2];

    const int tid = threadIdx.x;
    const int row0 = blockIdx.y * BM;
    const int col0 = blockIdx.x * BN;
    const int warp = tid >> 5, lane = tid & 31;
    const int gq = lane >> 2, tq = lane & 3;
    const int wm = (warp & 1) * 64;
    const int wn = (warp >> 1) * 32;
    const int nk = (K + BK - 1) / BK;

    float acc[4][4][4];
    #pragma unroll
    for (int a = 0; a < 4; a++)
        #pragma unroll
        for (int b = 0; b < 4; b++)
            #pragma unroll
            for (int c_ = 0; c_ < 4; c_++) acc[a][b][c_] = 0.f;

    uint32_t ra[8], rb[8];

    auto loadA = [&](int k0) {
        #pragma unroll
        for (int i = 0; i < 8; i++) {
            int e = i * 256 + tid;
            int r = e >> 4, k2 = e & 15;
            int gr = row0 + r, gk = k0 + 2 * k2;
            float v0 = 0.f, v1 = 0.f;
            if (gr < M && gk < K) {
                if (AM == 2) {
                    if (gk < NFEAT) {
                        int s = src[gr];
                        const float* p = &nodef[(long)s * NFEAT + gk];
                        v0 = p[0]; v1 = p[1];
                    } else {
                        const float* p = &edgef[(long)gr * NEFEAT + (gk - NFEAT)];
                        v0 = p[0]; v1 = p[1];
                    }
                } else {
                    const float2 p = *(const float2*)&A[(long)gr * lda + gk];
                    v0 = p.x; v1 = p.y;
                    if (AM == 1) {
                        v0 = v0 > 0.f ? v0 : expm1f(v0);
                        v1 = v1 > 0.f ? v1 : expm1f(v1);
                    }
                }
            }
            ra[i] = packbf(v0, v1);
        }
    };
    auto loadB = [&](int k0) {
        #pragma unroll
        for (int i = 0; i < 8; i++) {
            int e = i * 256 + tid;
            int k2 = e >> 7, n = e & 127;
            int gk = k0 + 2 * k2, gn = col0 + n;
            float v0 = 0.f, v1 = 0.f;
            if (gk < K && gn < N) {
                v0 = B[(long)gk * N + gn];
                v1 = B[(long)(gk + 1) * N + gn];
            }
            rb[i] = packbf(v0, v1);
        }
    };
    auto storeA = [&](int buf) {
        #pragma unroll
        for (int i = 0; i < 8; i++) {
            int e = i * 256 + tid;
            int r = e >> 4, k2 = e & 15;
            As[buf][r * SA + k2] = ra[i];
        }
    };
    auto storeB = [&](int buf) {
        #pragma unroll
        for (int i = 0; i < 8; i++) {
            int e = i * 256 + tid;
            int k2 = e >> 7, n = e & 127;
            Bs[buf][n * SB2 + k2] = rb[i];
        }
    };
    auto compute = [&](int buf) {
        #pragma unroll
        for (int ks = 0; ks < 2; ks++) {
            uint32_t af[4][4], bf[4][2];
            #pragma unroll
            for (int mt = 0; mt < 4; mt++) {
                int r = wm + mt * 16 + gq;
                int kb = ks * 8 + tq;
                af[mt][0] = As[buf][(r    ) * SA + kb    ];
                af[mt][1] = As[buf][(r + 8) * SA + kb    ];
                af[mt][2] = As[buf][(r    ) * SA + kb + 4];
                af[mt][3] = As[buf][(r + 8) * SA + kb + 4];
            }
            #pragma unroll
            for (int nt = 0; nt < 4; nt++) {
                int n = wn + nt * 8 + gq;
                int kb = ks * 8 + tq;
                bf[nt][0] = Bs[buf][n * SB2 + kb    ];
                bf[nt][1] = Bs[buf][n * SB2 + kb + 4];
            }
            #pragma unroll
            for (int mt = 0; mt < 4; mt++)
                #pragma unroll
                for (int nt = 0; nt < 4; nt++) {
                    asm volatile(
                        "mma.sync.aligned.m16n8k16.row.col.f32.bf16.bf16.f32 "
                        "{%0,%1,%2,%3},{%4,%5,%6,%7},{%8,%9},{%0,%1,%2,%3};"
                        : "+f"(acc[mt][nt][0]), "+f"(acc[mt][nt][1]),
                          "+f"(acc[mt][nt][2]), "+f"(acc[mt][nt][3])
                        : "r"(af[mt][0]), "r"(af[mt][1]), "r"(af[mt][2]), "r"(af[mt][3]),
                          "r"(bf[nt][0]), "r"(bf[nt][1]));
                }
        }
    };

    loadA(0); loadB(0);
    storeA(0); storeB(0);
    __syncthreads();
    for (int kt = 0; kt < nk; kt++) {
        int buf = kt & 1;
        if (kt + 1 < nk) { loadA((kt + 1) * BK); loadB((kt + 1) * BK); }
        compute(buf);
        if (kt + 1 < nk) {
            __syncthreads();
            storeA(buf ^ 1); storeB(buf ^ 1);
            __syncthreads();
        }
    }

    #pragma unroll
    for (int mt = 0; mt < 4; mt++) {
        int r0 = row0 + wm + mt * 16 + gq;
        int r1 = r0 + 8;
        #pragma unroll
        for (int nt = 0; nt < 4; nt++) {
            int cb = col0 + wn + nt * 8 + tq * 2;
            #pragma unroll
            for (int j = 0; j < 2; j++) {
                int cn = cb + j;
                if (cn >= N) continue;
                float bv = bias[cn];
                if (r0 < M) {
                    float v = acc[mt][nt][j] + bv;
                    if (EPI == 1) v = lreluf(v);
                    C[(long)r0 * N + cn] = v;
                }
                if (r1 < M) {
                    float v = acc[mt][nt][2 + j] + bv;
                    if (EPI == 1) v = lreluf(v);
                    C[(long)r1 * N + cn] = v;
                }
            }
        }
    }
}

// ---- per-node dot(s) ----
__global__ void node_dots_kernel(const float* __restrict__ X,
                                 const float* __restrict__ w0, const float* __restrict__ w1,
                                 float* __restrict__ out0, float* __restrict__ out1, int V)
{
    int warp = (blockIdx.x * blockDim.x + threadIdx.x) >> 5;
    int lane = threadIdx.x & 31;
    if (warp >= V) return;
    const float* x = X + (long)warp * GG;
    float s0 = 0.f, s1 = 0.f;
    for (int j = lane; j < GG; j += 32) {
        float xv = x[j];
        s0 += xv * w0[j];
        if (w1) s1 += xv * w1[j];
    }
    s0 = warp_sum(s0);
    if (w1) s1 = warp_sum(s1);
    if (lane == 0) {
        out0[warp] = s0;
        if (w1) out1[warp] = s1;
    }
}

// ---- context edge logit: lrelu(d0[dst] + he1[e].w + b) ----
__global__ void edge_ctx_logit_kernel(const float* __restrict__ he1,
                                      const float* __restrict__ w, const float* __restrict__ b,
                                      const float* __restrict__ d0, const int* __restrict__ dst,
                                      float* __restrict__ logit, int E)
{
    int warp = (blockIdx.x * blockDim.x + threadIdx.x) >> 5;
    int lane = threadIdx.x & 31;
    if (warp >= E) return;
    const float* x = he1 + (long)warp * GG;
    float s = 0.f;
    for (int j = lane; j < GG; j += 32) s += x[j] * w[j];
    s = warp_sum(s);
    if (lane == 0) logit[warp] = lreluf(d0[dst[warp]] + s + b[0]);
}

// ---- layer edge logit ----
__global__ void edge_layer_logit_kernel(const float* __restrict__ d0, const float* __restrict__ d1,
                                        const int* __restrict__ src, const int* __restrict__ dst,
                                        const float* __restrict__ b, float* __restrict__ logit, int E)
{
    int e = blockIdx.x * blockDim.x + threadIdx.x;
    if (e >= E) return;
    logit[e] = lreluf(d0[dst[e]] + d1[src[e]] + b[0]);
}

// ---- CSR edge softmax: warp per node ----
__global__ void softmax_csr_kernel(const float* __restrict__ logit,
                                   const int* __restrict__ rowptr, const int* __restrict__ csr,
                                   float* __restrict__ att, int V)
{
    int node = (blockIdx.x * blockDim.x + threadIdx.x) >> 5;
    int lane = threadIdx.x & 31;
    if (node >= V) return;
    int s0 = rowptr[node], s1 = rowptr[node + 1];
    if (s0 == s1) return;
    float m = -1e30f;
    for (int i = s0 + lane; i < s1; i += 32) m = fmaxf(m, logit[csr[i]]);
    m = warp_allmax(m);
    float s = 0.f;
    for (int i = s0 + lane; i < s1; i += 32) s += expf(logit[csr[i]] - m);
    s = warp_allsum(s);
    float inv = 1.f / s;
    for (int i = s0 + lane; i < s1; i += 32) {
        int e = csr[i];
        att[e] = expf(logit[e] - m) * inv;
    }
}

// ---- CSR gather: c[d] = sum_{e in in(d)} att[e] * X[row(e)]  (row = eid or src[eid]) ----
__global__ void gather_c_kernel(const float* __restrict__ X, const float* __restrict__ att,
                                const int* __restrict__ rowptr, const int* __restrict__ csr,
                                const int* __restrict__ srcmap,   // null -> row=eid
                                float* __restrict__ c, int V)
{
    int node = (blockIdx.x * blockDim.x + threadIdx.x) >> 5;
    int lane = threadIdx.x & 31;
    if (node >= V) return;
    int s0 = rowptr[node], s1 = rowptr[node + 1];
    float acc[7] = {0.f, 0.f, 0.f, 0.f, 0.f, 0.f, 0.f};
    for (int i = s0; i < s1; i++) {
        int e = csr[i];
        float a = att[e];
        long row = srcmap ? (long)srcmap[e] : (long)e;
        const float* x = X + row * GG;
        #pragma unroll
        for (int k = 0; k < 7; k++) {
            int j = lane + 32 * k;
            if (j < GG) acc[k] = fmaf(a, x[j], acc[k]);
        }
    }
    float* cd = c + (long)node * GG;
    #pragma unroll
    for (int k = 0; k < 7; k++) {
        int j = lane + 32 * k;
        if (j < GG) cd[j] = acc[k];
    }
}

// ---- GRU gates ----
__global__ void gru_gates_kernel(const float* __restrict__ gi, const float* __restrict__ gh,
                                 float* __restrict__ h, int V)
{
    int idx = blockIdx.x * blockDim.x + threadIdx.x;
    if (idx >= V * GG) return;
    int v = idx / GG, j = idx - v * GG;
    const float* gvi = gi + (long)v * 3 * GG;
    const float* gvh = gh + (long)v * 3 * GG;
    float r = sigmoidf_(gvi[j]          + gvh[j]);
    float z = sigmoidf_(gvi[j + GG]     + gvh[j + GG]);
    float n = tanhf   (gvi[j + 2 * GG] + r * gvh[j + 2 * GG]);
    float hv = h[idx];
    float o = (1.f - z) * n + z * hv;
    h[idx] = o > 0.f ? o : 0.f;
}

// ---- readout ----
__global__ void pred_kernel(const float* __restrict__ nf, const float* __restrict__ predW,
                            const float* __restrict__ predb, const float* __restrict__ mask,
                            const int* __restrict__ gids, float* __restrict__ out_atom,
                            float* __restrict__ gsum, int V)
{
    int warp = (blockIdx.x * blockDim.x + threadIdx.x) >> 5;
    int lane = threadIdx.x & 31;
    if (warp >= V) return;
    const float* x = nf + (long)warp * GG;
    float s = 0.f;
    for (int j = lane; j < GG; j += 32) s += x[j] * predW[j];
    s = warp_sum(s);
    if (lane == 0) {
        float ap = s + predb[0] + mask[warp];
        out_atom[warp] = ap;
        atomicAdd(&gsum[gids[warp]], exp10f(-ap));
    }
}
__global__ void final_kernel(const float* __restrict__ gsum, float* __restrict__ out, int NG) {
    int g = blockIdx.x * blockDim.x + threadIdx.x;
    if (g >= NG) return;
    out[g] = -log10f(gsum[g]);
}

// ---- host ----
static inline int cdiv(int a, int b) { return (a + b - 1) / b; }

extern "C" void kernel_launch(void* const* d_in, const int* in_sizes, int n_in,
                              void* d_out, int out_size)
{
    const float* node_feats = (const float*)d_in[0];
    const float* edge_feats = (const float*)d_in[1];
    const float* pn_W  = (const float*)d_in[2];
    const float* pn_b  = (const float*)d_in[3];
    const float* pe1_W = (const float*)d_in[4];
    const float* pe1_b = (const float*)d_in[5];
    const float* pe2_W = (const float*)d_in[6];
    const float* pe2_b = (const float*)d_in[7];
    const float* et_W  = (const float*)d_in[8];
    const float* et_b  = (const float*)d_in[9];
    const float* gru0_Wih = (const float*)d_in[10];
    const float* gru0_Whh = (const float*)d_in[11];
    const float* gru0_bih = (const float*)d_in[12];
    const float* gru0_bhh = (const float*)d_in[13];
    const float* gnn_pe_W = (const float*)d_in[14];
    const float* gnn_pe_b = (const float*)d_in[15];
    const float* gnn_pn_W = (const float*)d_in[16];
    const float* gnn_pn_b = (const float*)d_in[17];
    const float* gnn_gru_Wih = (const float*)d_in[18];
    const float* gnn_gru_Whh = (const float*)d_in[19];
    const float* gnn_gru_bih = (const float*)d_in[20];
    const float* gnn_gru_bhh = (const float*)d_in[21];
    const float* pred_W = (const float*)d_in[22];
    const float* pred_b = (const float*)d_in[23];
    const int* srci = (const int*)d_in[24];
    const int* dsti = (const int*)d_in[25];
    const int* gids = (const int*)d_in[26];

    int V = in_sizes[0] / NFEAT;
    int E = in_sizes[24];
    int NG = out_size - V;
    float* out = (float*)d_out;
    int L = in_sizes[15];

    float *hv, *he1, *c, *hvp, *gi, *gh, *maskp, *d0, *d1, *logit, *att, *gsum;
    int *rowptr, *cursor, *csr;
    cudaGetSymbolAddress((void**)&hv,    g_hv);
    cudaGetSymbolAddress((void**)&he1,   g_he1);
    cudaGetSymbolAddress((void**)&c,     g_c);
    cudaGetSymbolAddress((void**)&hvp,   g_hvp);
    cudaGetSymbolAddress((void**)&gi,    g_gi);
    cudaGetSymbolAddress((void**)&gh,    g_gh);
    cudaGetSymbolAddress((void**)&maskp, g_mask);
    cudaGetSymbolAddress((void**)&d0,    g_d0);
    cudaGetSymbolAddress((void**)&d1,    g_d1);
    cudaGetSymbolAddress((void**)&logit, g_logit);
    cudaGetSymbolAddress((void**)&att,   g_att);
    cudaGetSymbolAddress((void**)&gsum,  g_gsum);
    cudaGetSymbolAddress((void**)&rowptr,g_rowptr);
    cudaGetSymbolAddress((void**)&cursor,g_cursor);
    cudaGetSymbolAddress((void**)&csr,   g_csr);

    dim3 blk(256);
    int warpgridV = cdiv(V * 32, 256);

    // ---- CSR build ----
    fill_i_kernel<<<cdiv(V + 1, 256), blk>>>(rowptr, 0, V + 1);
    hist_kernel<<<cdiv(E, 256), blk>>>(dsti, rowptr, E);
    scan_kernel<<<1, 1024>>>(rowptr, V + 1);
    copy_i_kernel<<<cdiv(V, 256), blk>>>(rowptr, cursor, V);
    csr_scatter_kernel<<<cdiv(E, 256), blk>>>(dsti, cursor, csr, E);

    mask_kernel<<<cdiv(V, 256), blk>>>(node_feats, maskp, V);

    // hv_new = lrelu(node_feats @ pn_W + pn_b)
    {
        dim3 g(cdiv(GG, BN), cdiv(V, BM));
        mma_gemm_kernel<0, 1><<<g, blk>>>(node_feats, NFEAT, pn_W, pn_b, hv,
                                          V, GG, NFEAT, nullptr, nullptr, nullptr);
    }
    // he1 = lrelu(concat(node_feats[src], edge_feats) @ pe1_W + pe1_b)
    {
        dim3 g(cdiv(GG, BN), cdiv(E, BM));
        mma_gemm_kernel<2, 1><<<g, blk>>>(nullptr, 0, pe1_W, pe1_b, he1,
                                          E, GG, NFEAT + NEFEAT, node_feats, edge_feats, srci);
    }
    node_dots_kernel<<<warpgridV, blk>>>(hv, pe2_W, nullptr, d0, nullptr, V);
    edge_ctx_logit_kernel<<<cdiv(E * 32, 256), blk>>>(he1, pe2_W + GG, pe2_b, d0, dsti, logit, E);
    softmax_csr_kernel<<<warpgridV, blk>>>(logit, rowptr, csr, att, V);
    // he1 <- he1 @ et_W + et_b  (in-place; row r depends only on row r)
    {
        dim3 g(cdiv(GG, BN), cdiv(E, BM));
        mma_gemm_kernel<0, 0><<<g, blk>>>(he1, GG, et_W, et_b, he1,
                                          E, GG, GG, nullptr, nullptr, nullptr);
    }
    // c[d] = sum att[e] * he1[e]
    gather_c_kernel<<<warpgridV, blk>>>(he1, att, rowptr, csr, nullptr, c, V);
    // GRU0
    {
        dim3 g(cdiv(3 * GG, BN), cdiv(V, BM));
        mma_gemm_kernel<1, 0><<<g, blk>>>(c, GG, gru0_Wih, gru0_bih, gi,
                                          V, 3 * GG, GG, nullptr, nullptr, nullptr);
        mma_gemm_kernel<0, 0><<<g, blk>>>(hv, GG, gru0_Whh, gru0_bhh, gh,
                                          V, 3 * GG, GG, nullptr, nullptr, nullptr);
    }
    gru_gates_kernel<<<cdiv(V * GG, 256), blk>>>(gi, gh, hv, V);

    for (int l = 0; l < L; l++) {
        node_dots_kernel<<<warpgridV, blk>>>(hv, gnn_pe_W + (long)l * 2 * GG,
                                             gnn_pe_W + (long)l * 2 * GG + GG, d0, d1, V);
        edge_layer_logit_kernel<<<cdiv(E, 256), blk>>>(d0, d1, srci, dsti, gnn_pe_b + l, logit, E);
        softmax_csr_kernel<<<warpgridV, blk>>>(logit, rowptr, csr, att, V);
        {
            dim3 g(cdiv(GG, BN), cdiv(V, BM));
            mma_gemm_kernel<0, 0><<<g, blk>>>(hv, GG, gnn_pn_W + (long)l * GG * GG,
                                              gnn_pn_b + (long)l * GG, hvp,
                                              V, GG, GG, nullptr, nullptr, nullptr);
        }
        // c[d] = sum att[e] * hvp[src[e]]
        gather_c_kernel<<<warpgridV, blk>>>(hvp, att, rowptr, csr, srci, c, V);
        {
            dim3 g(cdiv(3 * GG, BN), cdiv(V, BM));
            mma_gemm_kernel<1, 0><<<g, blk>>>(c, GG, gnn_gru_Wih + (long)l * GG * 3 * GG,
                                              gnn_gru_bih + (long)l * 3 * GG, gi,
                                              V, 3 * GG, GG, nullptr, nullptr, nullptr);
            mma_gemm_kernel<0, 0><<<g, blk>>>(hv, GG, gnn_gru_Whh + (long)l * GG * 3 * GG,
                                              gnn_gru_bhh + (long)l * 3 * GG, gh,
                                              V, 3 * GG, GG, nullptr, nullptr, nullptr);
        }
        gru_gates_kernel<<<cdiv(V * GG, 256), blk>>>(gi, gh, hv, V);
    }

    fill_f_kernel<<<cdiv(NG, 256), blk>>>(gsum, 0.f, NG);
    pred_kernel<<<warpgridV, blk>>>(hv, pred_W, pred_b, maskp, gids, out + NG, gsum, V);
    final_kernel<<<cdiv(NG, 256), blk>>>(gsum, out, NG);
}

// round 5
// speedup vs baseline: 3.6497x; 1.4917x over previous
#include <cuda_runtime.h>
#include <cuda_bf16.h>
#include <math.h>
#include <stdint.h>

// ---- problem constants ----
#define VV 100000
#define EE 400000
#define GG 200
#define NFEAT 74
#define NEFEAT 12
#define NGMAX 8192

// ---- scratch ----
__device__ float          g_hv [VV * GG];
__device__ float          g_he1[EE * GG];
__device__ float          g_hvp[VV * GG];
__device__ float          g_gi [VV * 3 * GG];
__device__ float          g_gh [VV * 3 * GG];
__device__ __nv_bfloat16  g_hvb [VV * GG];
__device__ __nv_bfloat16  g_he1b[EE * GG];
__device__ __nv_bfloat16  g_cb  [VV * GG];
__device__ uint32_t       g_wb[430000];        // converted weights (bf16x2, transposed)
__device__ float          g_mask[VV];
__device__ float          g_d0[VV];
__device__ float          g_d1[VV];
__device__ float          g_logit[EE];
__device__ float          g_att[EE];
__device__ float          g_gsum[NGMAX];
__device__ int            g_rowptr[VV + 1];
__device__ int            g_cursor[VV];
__device__ int            g_csr[EE];

// ---- helpers ----
__device__ __forceinline__ float lreluf(float x) { return x > 0.f ? x : 0.01f * x; }
__device__ __forceinline__ float sigmoidf_(float x) { return 1.f / (1.f + expf(-x)); }
__device__ __forceinline__ float warp_sum(float v) {
    #pragma unroll
    for (int o = 16; o; o >>= 1) v += __shfl_down_sync(0xffffffffu, v, o);
    return v;
}
__device__ __forceinline__ float warp_allmax(float v) {
    #pragma unroll
    for (int o = 16; o; o >>= 1) v = fmaxf(v, __shfl_xor_sync(0xffffffffu, v, o));
    return v;
}
__device__ __forceinline__ float warp_allsum(float v) {
    #pragma unroll
    for (int o = 16; o; o >>= 1) v += __shfl_xor_sync(0xffffffffu, v, o);
    return v;
}
__device__ __forceinline__ uint32_t packbf(float lo, float hi) {
    __nv_bfloat162 p = __floats2bfloat162_rn(lo, hi);
    return *reinterpret_cast<uint32_t*>(&p);
}
__device__ __forceinline__ void cp_async16(uint32_t saddr, const void* g, int bytes) {
    asm volatile("cp.async.cg.shared.global [%0], [%1], 16, %2;"
                 :: "r"(saddr), "l"(g), "r"(bytes));
}
__device__ __forceinline__ void cp_commit() { asm volatile("cp.async.commit_group;"); }
template<int NN>
__device__ __forceinline__ void cp_wait() { asm volatile("cp.async.wait_group %0;" :: "n"(NN)); }

// ---- fills ----
__global__ void fill_f_kernel(float* p, float v, int n) {
    int i = blockIdx.x * blockDim.x + threadIdx.x;
    if (i < n) p[i] = v;
}
__global__ void fill_i_kernel(int* p, int v, int n) {
    int i = blockIdx.x * blockDim.x + threadIdx.x;
    if (i < n) p[i] = v;
}

// ---- weight conversion: W (K x N fp32, row-major) -> Bt (N x K/2 bf16x2) ----
__global__ void convw_kernel(const float* __restrict__ W, uint32_t* __restrict__ Bt,
                             int K, int N) {
    int idx = blockIdx.x * blockDim.x + threadIdx.x;
    int K2 = K >> 1;
    if (idx >= N * K2) return;
    int n = idx / K2, k2 = idx - n * K2;
    Bt[idx] = packbf(W[(long)(2 * k2) * N + n], W[(long)(2 * k2 + 1) * N + n]);
}

// ---- CSR build ----
__global__ void hist_kernel(const int* __restrict__ dst, int* __restrict__ rowptr, int E) {
    int e = blockIdx.x * blockDim.x + threadIdx.x;
    if (e < E) atomicAdd(&rowptr[dst[e] + 1], 1);
}
__global__ void scan_kernel(int* __restrict__ p, int n) {
    __shared__ int tsum[1024];
    int tid = threadIdx.x;
    int chunk = (n + 1023) / 1024;
    int s0 = tid * chunk, s1 = min(s0 + chunk, n);
    int sum = 0;
    for (int i = s0; i < s1; i++) sum += p[i];
    tsum[tid] = sum;
    __syncthreads();
    int val = tsum[tid];
    #pragma unroll
    for (int o = 1; o < 1024; o <<= 1) {
        int other = (tid >= o) ? tsum[tid - o] : 0;
        __syncthreads();
        val += other;
        tsum[tid] = val;
        __syncthreads();
    }
    int offset = (tid > 0) ? tsum[tid - 1] : 0;
    int run = offset;
    for (int i = s0; i < s1; i++) { run += p[i]; p[i] = run; }
}
__global__ void copy_i_kernel(const int* __restrict__ a, int* __restrict__ b, int n) {
    int i = blockIdx.x * blockDim.x + threadIdx.x;
    if (i < n) b[i] = a[i];
}
__global__ void csr_scatter_kernel(const int* __restrict__ dst, int* __restrict__ cursor,
                                   int* __restrict__ csr, int E) {
    int e = blockIdx.x * blockDim.x + threadIdx.x;
    if (e >= E) return;
    int pos = atomicAdd(&cursor[dst[e]], 1);
    csr[pos] = e;
}

// ---- mask ----
__global__ void mask_kernel(const float* __restrict__ nf, float* __restrict__ mask, int V) {
    int v = blockIdx.x * blockDim.x + threadIdx.x;
    if (v >= V) return;
    const float* r = nf + (long)v * NFEAT;
    float s = r[NFEAT - 4] + r[NFEAT - 3] + r[NFEAT - 2] + r[NFEAT - 1];
    float m = s * (1.f - r[0]);
    mask[v] = 1.f / m - 1.f;
}

#define BM 128
#define BN 128
#define BK 32
#define SA 20
#define SB2 20

// ============================================================
// Old-style GEMM for small-K (fp32 A loads + cvt). Writes fp32 C and optional bf16 Cb.
// AM: 0=direct, 2=concat. EPI: 1=lrelu.
// ============================================================
template<int AM, int EPI>
__global__ __launch_bounds__(256, 2)
void mma_gemm_kernel(const float* __restrict__ A, int lda,
                     const float* __restrict__ B,
                     const float* __restrict__ bias,
                     float* C, __nv_bfloat16* Cb,
                     int M, int N, int K,
                     const float* __restrict__ nodef, const float* __restrict__ edgef,
                     const int* __restrict__ src)
{
    __shared__ uint32_t As[2][BM * SA];
    __shared__ uint32_t Bs[2][BN * SB2];

    const int tid = threadIdx.x;
    const int row0 = blockIdx.y * BM;
    const int col0 = blockIdx.x * BN;
    const int warp = tid >> 5, lane = tid & 31;
    const int gq = lane >> 2, tq = lane & 3;
    const int wm = (warp & 1) * 64;
    const int wn = (warp >> 1) * 32;
    const int nk = (K + BK - 1) / BK;

    float acc[4][4][4];
    #pragma unroll
    for (int a = 0; a < 4; a++)
        #pragma unroll
        for (int b = 0; b < 4; b++)
            #pragma unroll
            for (int c_ = 0; c_ < 4; c_++) acc[a][b][c_] = 0.f;

    uint32_t ra[8], rb[8];

    auto loadA = [&](int k0) {
        #pragma unroll
        for (int i = 0; i < 8; i++) {
            int e = i * 256 + tid;
            int r = e >> 4, k2 = e & 15;
            int gr = row0 + r, gk = k0 + 2 * k2;
            float v0 = 0.f, v1 = 0.f;
            if (gr < M && gk < K) {
                if (AM == 2) {
                    if (gk < NFEAT) {
                        int s = src[gr];
                        const float* p = &nodef[(long)s * NFEAT + gk];
                        v0 = p[0]; v1 = p[1];
                    } else {
                        const float* p = &edgef[(long)gr * NEFEAT + (gk - NFEAT)];
                        v0 = p[0]; v1 = p[1];
                    }
                } else {
                    const float2 p = *(const float2*)&A[(long)gr * lda + gk];
                    v0 = p.x; v1 = p.y;
                }
            }
            ra[i] = packbf(v0, v1);
        }
    };
    auto loadB = [&](int k0) {
        #pragma unroll
        for (int i = 0; i < 8; i++) {
            int e = i * 256 + tid;
            int k2 = e >> 7, n = e & 127;
            int gk = k0 + 2 * k2, gn = col0 + n;
            float v0 = 0.f, v1 = 0.f;
            if (gk < K && gn < N) {
                v0 = B[(long)gk * N + gn];
                v1 = B[(long)(gk + 1) * N + gn];
            }
            rb[i] = packbf(v0, v1);
        }
    };
    auto storeA = [&](int buf) {
        #pragma unroll
        for (int i = 0; i < 8; i++) {
            int e = i * 256 + tid;
            As[buf][(e >> 4) * SA + (e & 15)] = ra[i];
        }
    };
    auto storeB = [&](int buf) {
        #pragma unroll
        for (int i = 0; i < 8; i++) {
            int e = i * 256 + tid;
            Bs[buf][(e & 127) * SB2 + (e >> 7)] = rb[i];
        }
    };
    auto compute = [&](int buf) {
        #pragma unroll
        for (int ks = 0; ks < 2; ks++) {
            uint32_t af[4][4], bf[4][2];
            #pragma unroll
            for (int mt = 0; mt < 4; mt++) {
                int r = wm + mt * 16 + gq;
                int kb = ks * 8 + tq;
                af[mt][0] = As[buf][(r    ) * SA + kb    ];
                af[mt][1] = As[buf][(r + 8) * SA + kb    ];
                af[mt][2] = As[buf][(r    ) * SA + kb + 4];
                af[mt][3] = As[buf][(r + 8) * SA + kb + 4];
            }
            #pragma unroll
            for (int nt = 0; nt < 4; nt++) {
                int n = wn + nt * 8 + gq;
                int kb = ks * 8 + tq;
                bf[nt][0] = Bs[buf][n * SB2 + kb    ];
                bf[nt][1] = Bs[buf][n * SB2 + kb + 4];
            }
            #pragma unroll
            for (int mt = 0; mt < 4; mt++)
                #pragma unroll
                for (int nt = 0; nt < 4; nt++) {
                    asm volatile(
                        "mma.sync.aligned.m16n8k16.row.col.f32.bf16.bf16.f32 "
                        "{%0,%1,%2,%3},{%4,%5,%6,%7},{%8,%9},{%0,%1,%2,%3};"
                        : "+f"(acc[mt][nt][0]), "+f"(acc[mt][nt][1]),
                          "+f"(acc[mt][nt][2]), "+f"(acc[mt][nt][3])
                        : "r"(af[mt][0]), "r"(af[mt][1]), "r"(af[mt][2]), "r"(af[mt][3]),
                          "r"(bf[nt][0]), "r"(bf[nt][1]));
                }
        }
    };

    loadA(0); loadB(0);
    storeA(0); storeB(0);
    __syncthreads();
    for (int kt = 0; kt < nk; kt++) {
        int buf = kt & 1;
        if (kt + 1 < nk) { loadA((kt + 1) * BK); loadB((kt + 1) * BK); }
        compute(buf);
        if (kt + 1 < nk) {
            __syncthreads();
            storeA(buf ^ 1); storeB(buf ^ 1);
            __syncthreads();
        }
    }

    #pragma unroll
    for (int mt = 0; mt < 4; mt++) {
        int rr[2] = { row0 + wm + mt * 16 + gq, row0 + wm + mt * 16 + gq + 8 };
        #pragma unroll
        for (int nt = 0; nt < 4; nt++) {
            int cb = col0 + wn + nt * 8 + tq * 2;
            #pragma unroll
            for (int h = 0; h < 2; h++) {
                if (rr[h] >= M) continue;
                #pragma unroll
                for (int j = 0; j < 2; j++) {
                    int cn = cb + j;
                    if (cn >= N) continue;
                    float v = acc[mt][nt][2 * h + j] + bias[cn];
                    if (EPI == 1) v = lreluf(v);
                    C[(long)rr[h] * N + cn] = v;
                    if (Cb) Cb[(long)rr[h] * N + cn] = __float2bfloat16(v);
                }
            }
        }
    }
}

// ============================================================
// BF16 GEMM with cp.async (A bf16 MxK row-major, Bt bf16x2 N x K/2)
// Requirements: K even, (K*2)%16==0 (K=200 ok).
// ============================================================
__global__ __launch_bounds__(256, 2)
void mma_bf16_kernel(const __nv_bfloat16* __restrict__ A,
                     const uint32_t* __restrict__ Bt,
                     const float* __restrict__ bias,
                     float* __restrict__ C,
                     int M, int N, int K)
{
    __shared__ uint32_t As[2][BM * SA];
    __shared__ uint32_t Bs[2][BN * SB2];

    const int tid = threadIdx.x;
    const int row0 = blockIdx.y * BM;
    const int col0 = blockIdx.x * BN;
    const int warp = tid >> 5, lane = tid & 31;
    const int gq = lane >> 2, tq = lane & 3;
    const int wm = (warp & 1) * 64;
    const int wn = (warp >> 1) * 32;
    const int K2 = K >> 1;
    const int nk = (K + BK - 1) / BK;

    const uint32_t sA = (uint32_t)__cvta_generic_to_shared(&As[0][0]);
    const uint32_t sB = (uint32_t)__cvta_generic_to_shared(&Bs[0][0]);

    float acc[4][4][4];
    #pragma unroll
    for (int a = 0; a < 4; a++)
        #pragma unroll
        for (int b = 0; b < 4; b++)
            #pragma unroll
            for (int c_ = 0; c_ < 4; c_++) acc[a][b][c_] = 0.f;

    auto issue = [&](int kt, int stage) {
        int k2t = kt * 16;
        #pragma unroll
        for (int i = 0; i < 2; i++) {
            int idx = i * 256 + tid;
            int r = idx >> 2, seg = idx & 3;
            int k2g = k2t + seg * 4;
            {
                int gr = row0 + r;
                bool ok = (gr < M) && (k2g < K2);
                int bytes = ok ? min(16, (K2 - k2g) * 4) : 0;
                const void* gp = ok ? (const void*)(A + (long)gr * K + 2 * k2g)
                                    : (const void*)A;
                cp_async16(sA + (stage * (BM * SA) + r * SA + seg * 4) * 4, gp, bytes);
            }
            {
                int gn = col0 + r;
                bool ok = (gn < N) && (k2g < K2);
                int bytes = ok ? min(16, (K2 - k2g) * 4) : 0;
                const void* gp = ok ? (const void*)(Bt + (long)gn * K2 + k2g)
                                    : (const void*)Bt;
                cp_async16(sB + (stage * (BN * SB2) + r * SB2 + seg * 4) * 4, gp, bytes);
            }
        }
        cp_commit();
    };
    auto compute = [&](int buf) {
        #pragma unroll
        for (int ks = 0; ks < 2; ks++) {
            uint32_t af[4][4], bf[4][2];
            #pragma unroll
            for (int mt = 0; mt < 4; mt++) {
                int r = wm + mt * 16 + gq;
                int kb = ks * 8 + tq;
                af[mt][0] = As[buf][(r    ) * SA + kb    ];
                af[mt][1] = As[buf][(r + 8) * SA + kb    ];
                af[mt][2] = As[buf][(r    ) * SA + kb + 4];
                af[mt][3] = As[buf][(r + 8) * SA + kb + 4];
            }
            #pragma unroll
            for (int nt = 0; nt < 4; nt++) {
                int n = wn + nt * 8 + gq;
                int kb = ks * 8 + tq;
                bf[nt][0] = Bs[buf][n * SB2 + kb    ];
                bf[nt][1] = Bs[buf][n * SB2 + kb + 4];
            }
            #pragma unroll
            for (int mt = 0; mt < 4; mt++)
                #pragma unroll
                for (int nt = 0; nt < 4; nt++) {
                    asm volatile(
                        "mma.sync.aligned.m16n8k16.row.col.f32.bf16.bf16.f32 "
                        "{%0,%1,%2,%3},{%4,%5,%6,%7},{%8,%9},{%0,%1,%2,%3};"
                        : "+f"(acc[mt][nt][0]), "+f"(acc[mt][nt][1]),
                          "+f"(acc[mt][nt][2]), "+f"(acc[mt][nt][3])
                        : "r"(af[mt][0]), "r"(af[mt][1]), "r"(af[mt][2]), "r"(af[mt][3]),
                          "r"(bf[nt][0]), "r"(bf[nt][1]));
                }
        }
    };

    issue(0, 0);
    for (int kt = 0; kt < nk; kt++) {
        if (kt + 1 < nk) {
            issue(kt + 1, (kt + 1) & 1);
            cp_wait<1>();
        } else {
            cp_wait<0>();
        }
        __syncthreads();
        compute(kt & 1);
        if (kt + 1 < nk) __syncthreads();
    }

    #pragma unroll
    for (int mt = 0; mt < 4; mt++) {
        int rr[2] = { row0 + wm + mt * 16 + gq, row0 + wm + mt * 16 + gq + 8 };
        #pragma unroll
        for (int nt = 0; nt < 4; nt++) {
            int cb = col0 + wn + nt * 8 + tq * 2;
            #pragma unroll
            for (int h = 0; h < 2; h++) {
                if (rr[h] >= M) continue;
                #pragma unroll
                for (int j = 0; j < 2; j++) {
                    int cn = cb + j;
                    if (cn >= N) continue;
                    C[(long)rr[h] * N + cn] = acc[mt][nt][2 * h + j] + bias[cn];
                }
            }
        }
    }
}

// ---- per-node dot(s) ----
__global__ void node_dots_kernel(const float* __restrict__ X,
                                 const float* __restrict__ w0, const float* __restrict__ w1,
                                 float* __restrict__ out0, float* __restrict__ out1, int V)
{
    int warp = (blockIdx.x * blockDim.x + threadIdx.x) >> 5;
    int lane = threadIdx.x & 31;
    if (warp >= V) return;
    const float* x = X + (long)warp * GG;
    float s0 = 0.f, s1 = 0.f;
    for (int j = lane; j < GG; j += 32) {
        float xv = x[j];
        s0 += xv * w0[j];
        if (w1) s1 += xv * w1[j];
    }
    s0 = warp_sum(s0);
    if (w1) s1 = warp_sum(s1);
    if (lane == 0) {
        out0[warp] = s0;
        if (w1) out1[warp] = s1;
    }
}

// ---- context edge logit ----
__global__ void edge_ctx_logit_kernel(const float* __restrict__ he1,
                                      const float* __restrict__ w, const float* __restrict__ b,
                                      const float* __restrict__ d0, const int* __restrict__ dst,
                                      float* __restrict__ logit, int E)
{
    int warp = (blockIdx.x * blockDim.x + threadIdx.x) >> 5;
    int lane = threadIdx.x & 31;
    if (warp >= E) return;
    const float* x = he1 + (long)warp * GG;
    float s = 0.f;
    for (int j = lane; j < GG; j += 32) s += x[j] * w[j];
    s = warp_sum(s);
    if (lane == 0) logit[warp] = lreluf(d0[dst[warp]] + s + b[0]);
}

// ---- layer edge logit ----
__global__ void edge_layer_logit_kernel(const float* __restrict__ d0, const float* __restrict__ d1,
                                        const int* __restrict__ src, const int* __restrict__ dst,
                                        const float* __restrict__ b, float* __restrict__ logit, int E)
{
    int e = blockIdx.x * blockDim.x + threadIdx.x;
    if (e >= E) return;
    logit[e] = lreluf(d0[dst[e]] + d1[src[e]] + b[0]);
}

// ---- CSR edge softmax ----
__global__ void softmax_csr_kernel(const float* __restrict__ logit,
                                   const int* __restrict__ rowptr, const int* __restrict__ csr,
                                   float* __restrict__ att, int V)
{
    int node = (blockIdx.x * blockDim.x + threadIdx.x) >> 5;
    int lane = threadIdx.x & 31;
    if (node >= V) return;
    int s0 = rowptr[node], s1 = rowptr[node + 1];
    if (s0 == s1) return;
    float m = -1e30f;
    for (int i = s0 + lane; i < s1; i += 32) m = fmaxf(m, logit[csr[i]]);
    m = warp_allmax(m);
    float s = 0.f;
    for (int i = s0 + lane; i < s1; i += 32) s += expf(logit[csr[i]] - m);
    s = warp_allsum(s);
    float inv = 1.f / s;
    for (int i = s0 + lane; i < s1; i += 32) {
        int e = csr[i];
        att[e] = expf(logit[e] - m) * inv;
    }
}

// ---- CSR gather: cb[d] = bf16(elu(sum att[e]*X[row(e)])) ----
__global__ void gather_c_kernel(const float* __restrict__ X, const float* __restrict__ att,
                                const int* __restrict__ rowptr, const int* __restrict__ csr,
                                const int* __restrict__ srcmap,
                                __nv_bfloat16* __restrict__ cb, int V)
{
    int node = (blockIdx.x * blockDim.x + threadIdx.x) >> 5;
    int lane = threadIdx.x & 31;
    if (node >= V) return;
    int s0 = rowptr[node], s1 = rowptr[node + 1];
    float acc[7] = {0.f, 0.f, 0.f, 0.f, 0.f, 0.f, 0.f};
    for (int i = s0; i < s1; i++) {
        int e = csr[i];
        float a = att[e];
        long row = srcmap ? (long)srcmap[e] : (long)e;
        const float* x = X + row * GG;
        #pragma unroll
        for (int k = 0; k < 7; k++) {
            int j = lane + 32 * k;
            if (j < GG) acc[k] = fmaf(a, x[j], acc[k]);
        }
    }
    __nv_bfloat16* cd = cb + (long)node * GG;
    #pragma unroll
    for (int k = 0; k < 7; k++) {
        int j = lane + 32 * k;
        if (j < GG) {
            float v = acc[k];
            v = v > 0.f ? v : expm1f(v);
            cd[j] = __float2bfloat16(v);
        }
    }
}

// ---- GRU gates (writes fp32 h and bf16 copy) ----
__global__ void gru_gates_kernel(const float* __restrict__ gi, const float* __restrict__ gh,
                                 float* __restrict__ h, __nv_bfloat16* __restrict__ hb, int V)
{
    int idx = blockIdx.x * blockDim.x + threadIdx.x;
    if (idx >= V * GG) return;
    int v = idx / GG, j = idx - v * GG;
    const float* gvi = gi + (long)v * 3 * GG;
    const float* gvh = gh + (long)v * 3 * GG;
    float r = sigmoidf_(gvi[j]          + gvh[j]);
    float z = sigmoidf_(gvi[j + GG]     + gvh[j + GG]);
    float n = tanhf   (gvi[j + 2 * GG] + r * gvh[j + 2 * GG]);
    float hv = h[idx];
    float o = (1.f - z) * n + z * hv;
    o = o > 0.f ? o : 0.f;
    h[idx] = o;
    hb[idx] = __float2bfloat16(o);
}

// ---- readout ----
__global__ void pred_kernel(const float* __restrict__ nf, const float* __restrict__ predW,
                            const float* __restrict__ predb, const float* __restrict__ mask,
                            const int* __restrict__ gids, float* __restrict__ out_atom,
                            float* __restrict__ gsum, int V)
{
    int warp = (blockIdx.x * blockDim.x + threadIdx.x) >> 5;
    int lane = threadIdx.x & 31;
    if (warp >= V) return;
    const float* x = nf + (long)warp * GG;
    float s = 0.f;
    for (int j = lane; j < GG; j += 32) s += x[j] * predW[j];
    s = warp_sum(s);
    if (lane == 0) {
        float ap = s + predb[0] + mask[warp];
        out_atom[warp] = ap;
        atomicAdd(&gsum[gids[warp]], exp10f(-ap));
    }
}
__global__ void final_kernel(const float* __restrict__ gsum, float* __restrict__ out, int NG) {
    int g = blockIdx.x * blockDim.x + threadIdx.x;
    if (g >= NG) return;
    out[g] = -log10f(gsum[g]);
}

// ---- host ----
static inline int cdiv(int a, int b) { return (a + b - 1) / b; }

extern "C" void kernel_launch(void* const* d_in, const int* in_sizes, int n_in,
                              void* d_out, int out_size)
{
    const float* node_feats = (const float*)d_in[0];
    const float* edge_feats = (const float*)d_in[1];
    const float* pn_W  = (const float*)d_in[2];
    const float* pn_b  = (const float*)d_in[3];
    const float* pe1_W = (const float*)d_in[4];
    const float* pe1_b = (const float*)d_in[5];
    const float* pe2_W = (const float*)d_in[6];
    const float* pe2_b = (const float*)d_in[7];
    const float* et_W  = (const float*)d_in[8];
    const float* et_b  = (const float*)d_in[9];
    const float* gru0_Wih = (const float*)d_in[10];
    const float* gru0_Whh = (const float*)d_in[11];
    const float* gru0_bih = (const float*)d_in[12];
    const float* gru0_bhh = (const float*)d_in[13];
    const float* gnn_pe_W = (const float*)d_in[14];
    const float* gnn_pe_b = (const float*)d_in[15];
    const float* gnn_pn_W = (const float*)d_in[16];
    const float* gnn_pn_b = (const float*)d_in[17];
    const float* gnn_gru_Wih = (const float*)d_in[18];
    const float* gnn_gru_Whh = (const float*)d_in[19];
    const float* gnn_gru_bih = (const float*)d_in[20];
    const float* gnn_gru_bhh = (const float*)d_in[21];
    const float* pred_W = (const float*)d_in[22];
    const float* pred_b = (const float*)d_in[23];
    const int* srci = (const int*)d_in[24];
    const int* dsti = (const int*)d_in[25];
    const int* gids = (const int*)d_in[26];

    int V = in_sizes[0] / NFEAT;
    int E = in_sizes[24];
    int NG = out_size - V;
    float* out = (float*)d_out;
    int L = in_sizes[15];

    float *hv, *he1, *hvp, *gi, *gh, *maskp, *d0, *d1, *logit, *att, *gsum;
    __nv_bfloat16 *hvb, *he1b, *cb;
    uint32_t* wb;
    int *rowptr, *cursor, *csr;
    cudaGetSymbolAddress((void**)&hv,    g_hv);
    cudaGetSymbolAddress((void**)&he1,   g_he1);
    cudaGetSymbolAddress((void**)&hvp,   g_hvp);
    cudaGetSymbolAddress((void**)&gi,    g_gi);
    cudaGetSymbolAddress((void**)&gh,    g_gh);
    cudaGetSymbolAddress((void**)&hvb,   g_hvb);
    cudaGetSymbolAddress((void**)&he1b,  g_he1b);
    cudaGetSymbolAddress((void**)&cb,    g_cb);
    cudaGetSymbolAddress((void**)&wb,    g_wb);
    cudaGetSymbolAddress((void**)&maskp, g_mask);
    cudaGetSymbolAddress((void**)&d0,    g_d0);
    cudaGetSymbolAddress((void**)&d1,    g_d1);
    cudaGetSymbolAddress((void**)&logit, g_logit);
    cudaGetSymbolAddress((void**)&att,   g_att);
    cudaGetSymbolAddress((void**)&gsum,  g_gsum);
    cudaGetSymbolAddress((void**)&rowptr,g_rowptr);
    cudaGetSymbolAddress((void**)&cursor,g_cursor);
    cudaGetSymbolAddress((void**)&csr,   g_csr);

    dim3 blk(256);
    int warpgridV = cdiv(V * 32, 256);

    // weight offsets (u32 units): K=200 GEMM weights, layout [N][K/2]
    const int OFF_ET = 0;                    // 200x200 -> 20000
    const int OFF_G0IH = 20000;              // 200x600 -> 60000
    const int OFF_G0HH = 80000;
    const int OFF_LAYER = 140000;            // per layer: pn 20000 + wih 60000 + whh 60000
    const int LAYER_STRIDE = 140000;

    // ---- weight conversion ----
    convw_kernel<<<cdiv(20000, 256), blk>>>(et_W, wb + OFF_ET, 200, 200);
    convw_kernel<<<cdiv(60000, 256), blk>>>(gru0_Wih, wb + OFF_G0IH, 200, 600);
    convw_kernel<<<cdiv(60000, 256), blk>>>(gru0_Whh, wb + OFF_G0HH, 200, 600);
    for (int l = 0; l < L; l++) {
        convw_kernel<<<cdiv(20000, 256), blk>>>(gnn_pn_W + (long)l * 200 * 200,
                                                wb + OFF_LAYER + l * LAYER_STRIDE, 200, 200);
        convw_kernel<<<cdiv(60000, 256), blk>>>(gnn_gru_Wih + (long)l * 200 * 600,
                                                wb + OFF_LAYER + l * LAYER_STRIDE + 20000, 200, 600);
        convw_kernel<<<cdiv(60000, 256), blk>>>(gnn_gru_Whh + (long)l * 200 * 600,
                                                wb + OFF_LAYER + l * LAYER_STRIDE + 80000, 200, 600);
    }

    // ---- CSR build ----
    fill_i_kernel<<<cdiv(V + 1, 256), blk>>>(rowptr, 0, V + 1);
    hist_kernel<<<cdiv(E, 256), blk>>>(dsti, rowptr, E);
    scan_kernel<<<1, 1024>>>(rowptr, V + 1);
    copy_i_kernel<<<cdiv(V, 256), blk>>>(rowptr, cursor, V);
    csr_scatter_kernel<<<cdiv(E, 256), blk>>>(dsti, cursor, csr, E);

    mask_kernel<<<cdiv(V, 256), blk>>>(node_feats, maskp, V);

    // hv = lrelu(node_feats @ pn_W + b)   (+ bf16 copy)
    {
        dim3 g(cdiv(GG, BN), cdiv(V, BM));
        mma_gemm_kernel<0, 1><<<g, blk>>>(node_feats, NFEAT, pn_W, pn_b, hv, hvb,
                                          V, GG, NFEAT, nullptr, nullptr, nullptr);
    }
    // he1 = lrelu(concat @ pe1_W + b)   (+ bf16 copy)
    {
        dim3 g(cdiv(GG, BN), cdiv(E, BM));
        mma_gemm_kernel<2, 1><<<g, blk>>>(nullptr, 0, pe1_W, pe1_b, he1, he1b,
                                          E, GG, NFEAT + NEFEAT, node_feats, edge_feats, srci);
    }
    node_dots_kernel<<<warpgridV, blk>>>(hv, pe2_W, nullptr, d0, nullptr, V);
    edge_ctx_logit_kernel<<<cdiv(E * 32, 256), blk>>>(he1, pe2_W + GG, pe2_b, d0, dsti, logit, E);
    softmax_csr_kernel<<<warpgridV, blk>>>(logit, rowptr, csr, att, V);
    // he1 <- he1b @ et_W + b (fp32 out, overwrites he1)
    {
        dim3 g(cdiv(GG, BN), cdiv(E, BM));
        mma_bf16_kernel<<<g, blk>>>(he1b, wb + OFF_ET, et_b, he1, E, GG, GG);
    }
    gather_c_kernel<<<warpgridV, blk>>>(he1, att, rowptr, csr, nullptr, cb, V);
    // GRU0
    {
        dim3 g(cdiv(3 * GG, BN), cdiv(V, BM));
        mma_bf16_kernel<<<g, blk>>>(cb, wb + OFF_G0IH, gru0_bih, gi, V, 3 * GG, GG);
        mma_bf16_kernel<<<g, blk>>>(hvb, wb + OFF_G0HH, gru0_bhh, gh, V, 3 * GG, GG);
    }
    gru_gates_kernel<<<cdiv(V * GG, 256), blk>>>(gi, gh, hv, hvb, V);

    for (int l = 0; l < L; l++) {
        node_dots_kernel<<<warpgridV, blk>>>(hv, gnn_pe_W + (long)l * 2 * GG,
                                             gnn_pe_W + (long)l * 2 * GG + GG, d0, d1, V);
        edge_layer_logit_kernel<<<cdiv(E, 256), blk>>>(d0, d1, srci, dsti, gnn_pe_b + l, logit, E);
        softmax_csr_kernel<<<warpgridV, blk>>>(logit, rowptr, csr, att, V);
        {
            dim3 g(cdiv(GG, BN), cdiv(V, BM));
            mma_bf16_kernel<<<g, blk>>>(hvb, wb + OFF_LAYER + l * LAYER_STRIDE,
                                        gnn_pn_b + (long)l * GG, hvp, V, GG, GG);
        }
        gather_c_kernel<<<warpgridV, blk>>>(hvp, att, rowptr, csr, srci, cb, V);
        {
            dim3 g(cdiv(3 * GG, BN), cdiv(V, BM));
            mma_bf16_kernel<<<g, blk>>>(cb, wb + OFF_LAYER + l * LAYER_STRIDE + 20000,
                                        gnn_gru_bih + (long)l * 3 * GG, gi, V, 3 * GG, GG);
            mma_bf16_kernel<<<g, blk>>>(hvb, wb + OFF_LAYER + l * LAYER_STRIDE + 80000,
                                        gnn_gru_bhh + (long)l * 3 * GG, gh, V, 3 * GG, GG);
        }
        gru_gates_kernel<<<cdiv(V * GG, 256), blk>>>(gi, gh, hv, hvb, V);
    }

    fill_f_kernel<<<cdiv(NG, 256), blk>>>(gsum, 0.f, NG);
    pred_kernel<<<warpgridV, blk>>>(hv, pred_W, pred_b, maskp, gids, out + NG, gsum, V);
    final_kernel<<<cdiv(NG, 256), blk>>>(gsum, out, NG);
}

// round 6
// speedup vs baseline: 5.3943x; 1.4780x over previous
#include <cuda_runtime.h>
#include <cuda_bf16.h>
#include <math.h>
#include <stdint.h>

// ---- problem constants ----
#define VV 100000
#define EE 400000
#define GG 200
#define NFEAT 74
#define NEFEAT 12
#define NGMAX 8192

// ---- scratch (all activations bf16) ----
__device__ __nv_bfloat16  g_hvb [VV * GG];
__device__ __nv_bfloat16  g_he1b[EE * GG];
__device__ __nv_bfloat16  g_he2b[EE * GG];
__device__ __nv_bfloat16  g_hvpb[VV * GG];
__device__ __nv_bfloat16  g_cb  [VV * GG];
__device__ __nv_bfloat16  g_gib [VV * 3 * GG];
__device__ __nv_bfloat16  g_ghb [VV * 3 * GG];
__device__ uint32_t       g_wb[430000];
__device__ float          g_mask[VV];
__device__ float          g_d0[VV];
__device__ float          g_d1[VV];
__device__ float          g_logit[EE];
__device__ float          g_att[EE];
__device__ float          g_gsum[NGMAX];
__device__ int            g_rowptr[VV + 1];
__device__ int            g_cursor[VV];
__device__ int            g_csr[EE];

// ---- helpers ----
__device__ __forceinline__ float lreluf(float x) { return x > 0.f ? x : 0.01f * x; }
__device__ __forceinline__ float sigmoidf_(float x) { return 1.f / (1.f + expf(-x)); }
__device__ __forceinline__ float warp_sum(float v) {
    #pragma unroll
    for (int o = 16; o; o >>= 1) v += __shfl_down_sync(0xffffffffu, v, o);
    return v;
}
__device__ __forceinline__ float warp_allmax(float v) {
    #pragma unroll
    for (int o = 16; o; o >>= 1) v = fmaxf(v, __shfl_xor_sync(0xffffffffu, v, o));
    return v;
}
__device__ __forceinline__ float warp_allsum(float v) {
    #pragma unroll
    for (int o = 16; o; o >>= 1) v += __shfl_xor_sync(0xffffffffu, v, o);
    return v;
}
__device__ __forceinline__ uint32_t packbf(float lo, float hi) {
    __nv_bfloat162 p = __floats2bfloat162_rn(lo, hi);
    return *reinterpret_cast<uint32_t*>(&p);
}
__device__ __forceinline__ void unpackbf(uint32_t u, float& lo, float& hi) {
    __nv_bfloat162 p = *reinterpret_cast<__nv_bfloat162*>(&u);
    lo = __bfloat162float(p.x);
    hi = __bfloat162float(p.y);
}
__device__ __forceinline__ void cp_async16(uint32_t saddr, const void* g, int bytes) {
    asm volatile("cp.async.cg.shared.global [%0], [%1], 16, %2;"
                 :: "r"(saddr), "l"(g), "r"(bytes));
}
__device__ __forceinline__ void cp_commit() { asm volatile("cp.async.commit_group;"); }
template<int NN>
__device__ __forceinline__ void cp_wait() { asm volatile("cp.async.wait_group %0;" :: "n"(NN)); }

// ---- fills ----
__global__ void fill_f_kernel(float* p, float v, int n) {
    int i = blockIdx.x * blockDim.x + threadIdx.x;
    if (i < n) p[i] = v;
}
__global__ void fill_i_kernel(int* p, int v, int n) {
    int i = blockIdx.x * blockDim.x + threadIdx.x;
    if (i < n) p[i] = v;
}

// ---- weight conversion: W (K x N fp32) -> Bt (N x K/2 bf16x2) ----
__global__ void convw_kernel(const float* __restrict__ W, uint32_t* __restrict__ Bt,
                             int K, int N) {
    int idx = blockIdx.x * blockDim.x + threadIdx.x;
    int K2 = K >> 1;
    if (idx >= N * K2) return;
    int n = idx / K2, k2 = idx - n * K2;
    Bt[idx] = packbf(W[(long)(2 * k2) * N + n], W[(long)(2 * k2 + 1) * N + n]);
}

// ---- CSR build ----
__global__ void hist_kernel(const int* __restrict__ dst, int* __restrict__ rowptr, int E) {
    int e = blockIdx.x * blockDim.x + threadIdx.x;
    if (e < E) atomicAdd(&rowptr[dst[e] + 1], 1);
}
__global__ void scan_kernel(int* __restrict__ p, int n) {
    __shared__ int tsum[1024];
    int tid = threadIdx.x;
    int chunk = (n + 1023) / 1024;
    int s0 = tid * chunk, s1 = min(s0 + chunk, n);
    int sum = 0;
    for (int i = s0; i < s1; i++) sum += p[i];
    tsum[tid] = sum;
    __syncthreads();
    int val = tsum[tid];
    #pragma unroll
    for (int o = 1; o < 1024; o <<= 1) {
        int other = (tid >= o) ? tsum[tid - o] : 0;
        __syncthreads();
        val += other;
        tsum[tid] = val;
        __syncthreads();
    }
    int offset = (tid > 0) ? tsum[tid - 1] : 0;
    int run = offset;
    for (int i = s0; i < s1; i++) { run += p[i]; p[i] = run; }
}
__global__ void copy_i_kernel(const int* __restrict__ a, int* __restrict__ b, int n) {
    int i = blockIdx.x * blockDim.x + threadIdx.x;
    if (i < n) b[i] = a[i];
}
__global__ void csr_scatter_kernel(const int* __restrict__ dst, int* __restrict__ cursor,
                                   int* __restrict__ csr, int E) {
    int e = blockIdx.x * blockDim.x + threadIdx.x;
    if (e >= E) return;
    int pos = atomicAdd(&cursor[dst[e]], 1);
    csr[pos] = e;
}

// ---- mask ----
__global__ void mask_kernel(const float* __restrict__ nf, float* __restrict__ mask, int V) {
    int v = blockIdx.x * blockDim.x + threadIdx.x;
    if (v >= V) return;
    const float* r = nf + (long)v * NFEAT;
    float s = r[NFEAT - 4] + r[NFEAT - 3] + r[NFEAT - 2] + r[NFEAT - 1];
    float m = s * (1.f - r[0]);
    mask[v] = 1.f / m - 1.f;
}

#define BM 128
#define BN 128
#define BK 32
#define SA 20
#define GSTG 3
#define GTSZ (128 * SA)   // u32 per matrix per stage

// ============================================================
// Main bf16 GEMM (K=200 path): 128x128 CTA, 4 warps x 64x64,
// 3-stage cp.async (1 sync/ktile), ldmatrix fragment loads.
// A: bf16 MxK row-major. Bt: bf16x2 [N][K/2]. C: bf16 (bias added fp32).
// ============================================================
__global__ __launch_bounds__(128, 2)
void mma_bf16_kernel(const __nv_bfloat16* __restrict__ A,
                     const uint32_t* __restrict__ Bt,
                     const float* __restrict__ bias,
                     __nv_bfloat16* __restrict__ C,
                     int M, int N, int K)
{
    extern __shared__ uint32_t smdyn[];
    uint32_t* Asm = smdyn;
    uint32_t* Bsm = smdyn + GSTG * GTSZ;

    const int tid = threadIdx.x;
    const int row0 = blockIdx.y * BM;
    const int col0 = blockIdx.x * BN;
    const int warp = tid >> 5, lane = tid & 31;
    const int wm = (warp & 1) * 64, wn = (warp >> 1) * 64;
    const int gq = lane >> 2, tq = lane & 3;
    const int K2 = K >> 1;
    const int nk = (K + BK - 1) / BK;

    const uint32_t sA0 = (uint32_t)__cvta_generic_to_shared(Asm);
    const uint32_t sB0 = (uint32_t)__cvta_generic_to_shared(Bsm);

    float acc[4][8][4] = {};

    auto issue = [&](int kt, int s) {
        int k2t = kt * 16;
        #pragma unroll
        for (int i = 0; i < 4; i++) {
            int idx = i * 128 + tid;
            int r = idx >> 2, seg = idx & 3;
            int k2g = k2t + seg * 4;
            {
                int gr = row0 + r;
                bool ok = (gr < M) && (k2g < K2);
                int bytes = ok ? min(16, (K2 - k2g) * 4) : 0;
                const void* gp = ok ? (const void*)(A + (long)gr * K + 2 * k2g)
                                    : (const void*)A;
                cp_async16(sA0 + (s * GTSZ + r * SA + seg * 4) * 4, gp, bytes);
            }
            {
                int gn = col0 + r;
                bool ok = (gn < N) && (k2g < K2);
                int bytes = ok ? min(16, (K2 - k2g) * 4) : 0;
                const void* gp = ok ? (const void*)(Bt + (long)gn * K2 + k2g)
                                    : (const void*)Bt;
                cp_async16(sB0 + (s * GTSZ + r * SA + seg * 4) * 4, gp, bytes);
            }
        }
        cp_commit();
    };

    // ldmatrix lane addressing
    const int rowA  = (lane & 7) + (lane & 8);        // tiles: m0,m8 | k0,k8
    const int kaddA = (lane & 16) >> 2;
    const int rowB  = (lane & 7) + ((lane & 16) >> 1); // tiles: n0k0,n0k8,n8k0,n8k8
    const int kaddB = (lane & 8) >> 1;

    auto compute = [&](int s) {
        #pragma unroll
        for (int ks = 0; ks < 2; ks++) {
            uint32_t af[4][4], bf[8][2];
            #pragma unroll
            for (int mt = 0; mt < 4; mt++) {
                uint32_t addr = sA0 + (s * GTSZ + (wm + mt * 16 + rowA) * SA + 8 * ks + kaddA) * 4;
                asm volatile("ldmatrix.sync.aligned.m8n8.x4.shared.b16 {%0,%1,%2,%3}, [%4];"
                    : "=r"(af[mt][0]), "=r"(af[mt][1]), "=r"(af[mt][2]), "=r"(af[mt][3])
                    : "r"(addr));
            }
            #pragma unroll
            for (int np = 0; np < 4; np++) {
                uint32_t addr = sB0 + (s * GTSZ + (wn + np * 16 + rowB) * SA + 8 * ks + kaddB) * 4;
                asm volatile("ldmatrix.sync.aligned.m8n8.x4.shared.b16 {%0,%1,%2,%3}, [%4];"
                    : "=r"(bf[2 * np][0]), "=r"(bf[2 * np][1]),
                      "=r"(bf[2 * np + 1][0]), "=r"(bf[2 * np + 1][1])
                    : "r"(addr));
            }
            #pragma unroll
            for (int mt = 0; mt < 4; mt++)
                #pragma unroll
                for (int nt = 0; nt < 8; nt++) {
                    asm volatile(
                        "mma.sync.aligned.m16n8k16.row.col.f32.bf16.bf16.f32 "
                        "{%0,%1,%2,%3},{%4,%5,%6,%7},{%8,%9},{%0,%1,%2,%3};"
                        : "+f"(acc[mt][nt][0]), "+f"(acc[mt][nt][1]),
                          "+f"(acc[mt][nt][2]), "+f"(acc[mt][nt][3])
                        : "r"(af[mt][0]), "r"(af[mt][1]), "r"(af[mt][2]), "r"(af[mt][3]),
                          "r"(bf[nt][0]), "r"(bf[nt][1]));
                }
        }
    };

    issue(0, 0);
    if (nk > 1) issue(1, 1);
    for (int kt = 0; kt < nk; kt++) {
        if (kt < nk - 1) cp_wait<1>(); else cp_wait<0>();
        __syncthreads();
        if (kt + 2 < nk) issue(kt + 2, (kt + 2) % GSTG);
        compute(kt % GSTG);
    }

    // epilogue: bf16x2 stores
    #pragma unroll
    for (int mt = 0; mt < 4; mt++) {
        int r0 = row0 + wm + mt * 16 + gq;
        int r1 = r0 + 8;
        #pragma unroll
        for (int nt = 0; nt < 8; nt++) {
            int cn = col0 + wn + nt * 8 + tq * 2;
            if (cn >= N) continue;
            float b0 = bias[cn], b1 = bias[cn + 1];
            if (r0 < M)
                *(uint32_t*)&C[(long)r0 * N + cn] = packbf(acc[mt][nt][0] + b0, acc[mt][nt][1] + b1);
            if (r1 < M)
                *(uint32_t*)&C[(long)r1 * N + cn] = packbf(acc[mt][nt][2] + b0, acc[mt][nt][3] + b1);
        }
    }
}

// ============================================================
// Small-K GEMM (fp32 inputs, cvt on store). Writes bf16 C with lrelu.
// AM: 0=direct, 2=concat [node_feats[src[row]] | edge_feats[row]]
// ============================================================
#define SB2 20
template<int AM>
__global__ __launch_bounds__(256, 2)
void mma_smallk_kernel(const float* __restrict__ A, int lda,
                       const float* __restrict__ B,
                       const float* __restrict__ bias,
                       __nv_bfloat16* __restrict__ Cb,
                       int M, int N, int K,
                       const float* __restrict__ nodef, const float* __restrict__ edgef,
                       const int* __restrict__ src)
{
    __shared__ uint32_t As[2][BM * SA];
    __shared__ uint32_t Bs[2][BN * SB2];

    const int tid = threadIdx.x;
    const int row0 = blockIdx.y * BM;
    const int col0 = blockIdx.x * BN;
    const int warp = tid >> 5, lane = tid & 31;
    const int gq = lane >> 2, tq = lane & 3;
    const int wm = (warp & 1) * 64;
    const int wn = (warp >> 1) * 32;
    const int nk = (K + BK - 1) / BK;

    float acc[4][4][4] = {};
    uint32_t ra[8], rb[8];

    auto loadA = [&](int k0) {
        #pragma unroll
        for (int i = 0; i < 8; i++) {
            int e = i * 256 + tid;
            int r = e >> 4, k2 = e & 15;
            int gr = row0 + r, gk = k0 + 2 * k2;
            float v0 = 0.f, v1 = 0.f;
            if (gr < M && gk < K) {
                if (AM == 2) {
                    if (gk < NFEAT) {
                        int s = src[gr];
                        const float* p = &nodef[(long)s * NFEAT + gk];
                        v0 = p[0]; v1 = p[1];
                    } else {
                        const float* p = &edgef[(long)gr * NEFEAT + (gk - NFEAT)];
                        v0 = p[0]; v1 = p[1];
                    }
                } else {
                    const float2 p = *(const float2*)&A[(long)gr * lda + gk];
                    v0 = p.x; v1 = p.y;
                }
            }
            ra[i] = packbf(v0, v1);
        }
    };
    auto loadB = [&](int k0) {
        #pragma unroll
        for (int i = 0; i < 8; i++) {
            int e = i * 256 + tid;
            int k2 = e >> 7, n = e & 127;
            int gk = k0 + 2 * k2, gn = col0 + n;
            float v0 = 0.f, v1 = 0.f;
            if (gk < K && gn < N) {
                v0 = B[(long)gk * N + gn];
                v1 = B[(long)(gk + 1) * N + gn];
            }
            rb[i] = packbf(v0, v1);
        }
    };
    auto storeA = [&](int buf) {
        #pragma unroll
        for (int i = 0; i < 8; i++) {
            int e = i * 256 + tid;
            As[buf][(e >> 4) * SA + (e & 15)] = ra[i];
        }
    };
    auto storeB = [&](int buf) {
        #pragma unroll
        for (int i = 0; i < 8; i++) {
            int e = i * 256 + tid;
            Bs[buf][(e & 127) * SB2 + (e >> 7)] = rb[i];
        }
    };
    auto compute = [&](int buf) {
        #pragma unroll
        for (int ks = 0; ks < 2; ks++) {
            uint32_t af[4][4], bf[4][2];
            #pragma unroll
            for (int mt = 0; mt < 4; mt++) {
                int r = wm + mt * 16 + gq;
                int kb = ks * 8 + tq;
                af[mt][0] = As[buf][(r    ) * SA + kb    ];
                af[mt][1] = As[buf][(r + 8) * SA + kb    ];
                af[mt][2] = As[buf][(r    ) * SA + kb + 4];
                af[mt][3] = As[buf][(r + 8) * SA + kb + 4];
            }
            #pragma unroll
            for (int nt = 0; nt < 4; nt++) {
                int n = wn + nt * 8 + gq;
                int kb = ks * 8 + tq;
                bf[nt][0] = Bs[buf][n * SB2 + kb    ];
                bf[nt][1] = Bs[buf][n * SB2 + kb + 4];
            }
            #pragma unroll
            for (int mt = 0; mt < 4; mt++)
                #pragma unroll
                for (int nt = 0; nt < 4; nt++) {
                    asm volatile(
                        "mma.sync.aligned.m16n8k16.row.col.f32.bf16.bf16.f32 "
                        "{%0,%1,%2,%3},{%4,%5,%6,%7},{%8,%9},{%0,%1,%2,%3};"
                        : "+f"(acc[mt][nt][0]), "+f"(acc[mt][nt][1]),
                          "+f"(acc[mt][nt][2]), "+f"(acc[mt][nt][3])
                        : "r"(af[mt][0]), "r"(af[mt][1]), "r"(af[mt][2]), "r"(af[mt][3]),
                          "r"(bf[nt][0]), "r"(bf[nt][1]));
                }
        }
    };

    loadA(0); loadB(0);
    storeA(0); storeB(0);
    __syncthreads();
    for (int kt = 0; kt < nk; kt++) {
        int buf = kt & 1;
        if (kt + 1 < nk) { loadA((kt + 1) * BK); loadB((kt + 1) * BK); }
        compute(buf);
        if (kt + 1 < nk) {
            __syncthreads();
            storeA(buf ^ 1); storeB(buf ^ 1);
            __syncthreads();
        }
    }

    #pragma unroll
    for (int mt = 0; mt < 4; mt++) {
        int rr[2] = { row0 + wm + mt * 16 + gq, row0 + wm + mt * 16 + gq + 8 };
        #pragma unroll
        for (int nt = 0; nt < 4; nt++) {
            int cn = col0 + wn + nt * 8 + tq * 2;
            if (cn >= N) continue;
            float b0 = bias[cn], b1 = bias[cn + 1];
            #pragma unroll
            for (int h = 0; h < 2; h++) {
                if (rr[h] >= M) continue;
                float v0 = lreluf(acc[mt][nt][2 * h] + b0);
                float v1 = lreluf(acc[mt][nt][2 * h + 1] + b1);
                *(uint32_t*)&Cb[(long)rr[h] * N + cn] = packbf(v0, v1);
            }
        }
    }
}

// ---- per-node dot (bf16 X) ----
__global__ void node_dots_kernel(const __nv_bfloat16* __restrict__ X,
                                 const float* __restrict__ w0,
                                 float* __restrict__ out0, int V)
{
    int node = (blockIdx.x * blockDim.x + threadIdx.x) >> 5;
    int lane = threadIdx.x & 31;
    if (node >= V) return;
    const uint32_t* x = (const uint32_t*)(X + (long)node * GG);
    float s0 = 0.f;
    #pragma unroll
    for (int k = 0; k < 4; k++) {
        int j2 = lane + 32 * k;
        if (j2 < GG / 2) {
            float lo, hi; unpackbf(x[j2], lo, hi);
            s0 += lo * w0[2 * j2] + hi * w0[2 * j2 + 1];
        }
    }
    s0 = warp_sum(s0);
    if (lane == 0) out0[node] = s0;
}

// ---- context edge logit: lrelu(d0[dst] + he1b[e].w + b) ----
__global__ void edge_ctx_logit_kernel(const __nv_bfloat16* __restrict__ he1b,
                                      const float* __restrict__ w, const float* __restrict__ b,
                                      const float* __restrict__ d0, const int* __restrict__ dst,
                                      float* __restrict__ logit, int E)
{
    int e = (blockIdx.x * blockDim.x + threadIdx.x) >> 5;
    int lane = threadIdx.x & 31;
    if (e >= E) return;
    const uint32_t* x = (const uint32_t*)(he1b + (long)e * GG);
    float s = 0.f;
    #pragma unroll
    for (int k = 0; k < 4; k++) {
        int j2 = lane + 32 * k;
        if (j2 < GG / 2) {
            float lo, hi; unpackbf(x[j2], lo, hi);
            s += lo * w[2 * j2] + hi * w[2 * j2 + 1];
        }
    }
    s = warp_sum(s);
    if (lane == 0) logit[e] = lreluf(d0[dst[e]] + s + b[0]);
}

// ---- layer edge logit ----
__global__ void edge_layer_logit_kernel(const float* __restrict__ d0, const float* __restrict__ d1,
                                        const int* __restrict__ src, const int* __restrict__ dst,
                                        const float* __restrict__ b, float* __restrict__ logit, int E)
{
    int e = blockIdx.x * blockDim.x + threadIdx.x;
    if (e >= E) return;
    logit[e] = lreluf(d0[dst[e]] + d1[src[e]] + b[0]);
}

// ---- CSR edge softmax ----
__global__ void softmax_csr_kernel(const float* __restrict__ logit,
                                   const int* __restrict__ rowptr, const int* __restrict__ csr,
                                   float* __restrict__ att, int V)
{
    int node = (blockIdx.x * blockDim.x + threadIdx.x) >> 5;
    int lane = threadIdx.x & 31;
    if (node >= V) return;
    int s0 = rowptr[node], s1 = rowptr[node + 1];
    if (s0 == s1) return;
    float m = -1e30f;
    for (int i = s0 + lane; i < s1; i += 32) m = fmaxf(m, logit[csr[i]]);
    m = warp_allmax(m);
    float s = 0.f;
    for (int i = s0 + lane; i < s1; i += 32) s += expf(logit[csr[i]] - m);
    s = warp_allsum(s);
    float inv = 1.f / s;
    for (int i = s0 + lane; i < s1; i += 32) {
        int e = csr[i];
        att[e] = expf(logit[e] - m) * inv;
    }
}

// ---- CSR gather: cb[d] = bf16(elu(sum att[e]*X[row(e)])), X bf16 ----
__global__ void gather_c_kernel(const __nv_bfloat16* __restrict__ X, const float* __restrict__ att,
                                const int* __restrict__ rowptr, const int* __restrict__ csr,
                                const int* __restrict__ srcmap,
                                __nv_bfloat16* __restrict__ cb, int V)
{
    int node = (blockIdx.x * blockDim.x + threadIdx.x) >> 5;
    int lane = threadIdx.x & 31;
    if (node >= V) return;
    int s0 = rowptr[node], s1 = rowptr[node + 1];
    float accx[4] = {0.f, 0.f, 0.f, 0.f};
    float accy[4] = {0.f, 0.f, 0.f, 0.f};
    for (int i = s0; i < s1; i++) {
        int e = csr[i];
        float a = att[e];
        long row = srcmap ? (long)srcmap[e] : (long)e;
        const uint32_t* x = (const uint32_t*)(X + row * GG);
        #pragma unroll
        for (int k = 0; k < 4; k++) {
            int j2 = lane + 32 * k;
            if (j2 < GG / 2) {
                float lo, hi; unpackbf(x[j2], lo, hi);
                accx[k] = fmaf(a, lo, accx[k]);
                accy[k] = fmaf(a, hi, accy[k]);
            }
        }
    }
    uint32_t* cd = (uint32_t*)(cb + (long)node * GG);
    #pragma unroll
    for (int k = 0; k < 4; k++) {
        int j2 = lane + 32 * k;
        if (j2 < GG / 2) {
            float lo = accx[k], hi = accy[k];
            lo = lo > 0.f ? lo : expm1f(lo);
            hi = hi > 0.f ? hi : expm1f(hi);
            cd[j2] = packbf(lo, hi);
        }
    }
}

// ---- fused GRU gates + (next-layer dots | pKa readout), warp per node ----
// mode 0: writes d0[v], d1[v] with weights w0, w1.
// mode 1: pred readout (w0=predW): out_atom[v], atomicAdd gsum.
__global__ void gru_gates_fused(const __nv_bfloat16* __restrict__ gib,
                                const __nv_bfloat16* __restrict__ ghb,
                                __nv_bfloat16* __restrict__ hb,
                                const float* __restrict__ w0, const float* __restrict__ w1,
                                float* __restrict__ d0, float* __restrict__ d1,
                                const float* __restrict__ predb, const float* __restrict__ mask,
                                const int* __restrict__ gids, float* __restrict__ out_atom,
                                float* __restrict__ gsum, int V, int mode)
{
    int v = (blockIdx.x * blockDim.x + threadIdx.x) >> 5;
    int lane = threadIdx.x & 31;
    if (v >= V) return;
    const uint32_t* gi = (const uint32_t*)(gib + (long)v * 3 * GG);  // 300 u32
    const uint32_t* gh = (const uint32_t*)(ghb + (long)v * 3 * GG);
    uint32_t* h = (uint32_t*)(hb + (long)v * GG);                    // 100 u32
    float s0 = 0.f, s1 = 0.f;
    #pragma unroll
    for (int k = 0; k < 4; k++) {
        int j2 = lane + 32 * k;
        if (j2 >= GG / 2) continue;
        float ir0, ir1, iz0, iz1, in0, in1, hr0, hr1, hz0, hz1, hn0, hn1, ho0, ho1;
        unpackbf(gi[j2], ir0, ir1);
        unpackbf(gi[j2 + 100], iz0, iz1);
        unpackbf(gi[j2 + 200], in0, in1);
        unpackbf(gh[j2], hr0, hr1);
        unpackbf(gh[j2 + 100], hz0, hz1);
        unpackbf(gh[j2 + 200], hn0, hn1);
        unpackbf(h[j2], ho0, ho1);
        float r0 = sigmoidf_(ir0 + hr0), r1 = sigmoidf_(ir1 + hr1);
        float z0 = sigmoidf_(iz0 + hz0), z1 = sigmoidf_(iz1 + hz1);
        float n0 = tanhf(in0 + r0 * hn0), n1 = tanhf(in1 + r1 * hn1);
        float o0 = (1.f - z0) * n0 + z0 * ho0;
        float o1 = (1.f - z1) * n1 + z1 * ho1;
        o0 = o0 > 0.f ? o0 : 0.f;
        o1 = o1 > 0.f ? o1 : 0.f;
        h[j2] = packbf(o0, o1);
        s0 += o0 * w0[2 * j2] + o1 * w0[2 * j2 + 1];
        if (mode == 0) s1 += o0 * w1[2 * j2] + o1 * w1[2 * j2 + 1];
    }
    s0 = warp_sum(s0);
    if (mode == 0) s1 = warp_sum(s1);
    if (lane == 0) {
        if (mode == 0) {
            d0[v] = s0;
            d1[v] = s1;
        } else {
            float ap = s0 + predb[0] + mask[v];
            out_atom[v] = ap;
            atomicAdd(&gsum[gids[v]], exp10f(-ap));
        }
    }
}

__global__ void final_kernel(const float* __restrict__ gsum, float* __restrict__ out, int NG) {
    int g = blockIdx.x * blockDim.x + threadIdx.x;
    if (g >= NG) return;
    out[g] = -log10f(gsum[g]);
}

// ---- host ----
static inline int cdiv(int a, int b) { return (a + b - 1) / b; }
#define GEMM_SMEM (GSTG * 2 * GTSZ * 4)

extern "C" void kernel_launch(void* const* d_in, const int* in_sizes, int n_in,
                              void* d_out, int out_size)
{
    const float* node_feats = (const float*)d_in[0];
    const float* edge_feats = (const float*)d_in[1];
    const float* pn_W  = (const float*)d_in[2];
    const float* pn_b  = (const float*)d_in[3];
    const float* pe1_W = (const float*)d_in[4];
    const float* pe1_b = (const float*)d_in[5];
    const float* pe2_W = (const float*)d_in[6];
    const float* pe2_b = (const float*)d_in[7];
    const float* et_W  = (const float*)d_in[8];
    const float* et_b  = (const float*)d_in[9];
    const float* gru0_Wih = (const float*)d_in[10];
    const float* gru0_Whh = (const float*)d_in[11];
    const float* gru0_bih = (const float*)d_in[12];
    const float* gru0_bhh = (const float*)d_in[13];
    const float* gnn_pe_W = (const float*)d_in[14];
    const float* gnn_pe_b = (const float*)d_in[15];
    const float* gnn_pn_W = (const float*)d_in[16];
    const float* gnn_pn_b = (const float*)d_in[17];
    const float* gnn_gru_Wih = (const float*)d_in[18];
    const float* gnn_gru_Whh = (const float*)d_in[19];
    const float* gnn_gru_bih = (const float*)d_in[20];
    const float* gnn_gru_bhh = (const float*)d_in[21];
    const float* pred_W = (const float*)d_in[22];
    const float* pred_b = (const float*)d_in[23];
    const int* srci = (const int*)d_in[24];
    const int* dsti = (const int*)d_in[25];
    const int* gids = (const int*)d_in[26];

    int V = in_sizes[0] / NFEAT;
    int E = in_sizes[24];
    int NG = out_size - V;
    float* out = (float*)d_out;
    int L = in_sizes[15];

    __nv_bfloat16 *hvb, *he1b, *he2b, *hvpb, *cb, *gib, *ghb;
    float *maskp, *d0, *d1, *logit, *att, *gsum;
    uint32_t* wb;
    int *rowptr, *cursor, *csr;
    cudaGetSymbolAddress((void**)&hvb,   g_hvb);
    cudaGetSymbolAddress((void**)&he1b,  g_he1b);
    cudaGetSymbolAddress((void**)&he2b,  g_he2b);
    cudaGetSymbolAddress((void**)&hvpb,  g_hvpb);
    cudaGetSymbolAddress((void**)&cb,    g_cb);
    cudaGetSymbolAddress((void**)&gib,   g_gib);
    cudaGetSymbolAddress((void**)&ghb,   g_ghb);
    cudaGetSymbolAddress((void**)&wb,    g_wb);
    cudaGetSymbolAddress((void**)&maskp, g_mask);
    cudaGetSymbolAddress((void**)&d0,    g_d0);
    cudaGetSymbolAddress((void**)&d1,    g_d1);
    cudaGetSymbolAddress((void**)&logit, g_logit);
    cudaGetSymbolAddress((void**)&att,   g_att);
    cudaGetSymbolAddress((void**)&gsum,  g_gsum);
    cudaGetSymbolAddress((void**)&rowptr,g_rowptr);
    cudaGetSymbolAddress((void**)&cursor,g_cursor);
    cudaGetSymbolAddress((void**)&csr,   g_csr);

    cudaFuncSetAttribute(mma_bf16_kernel, cudaFuncAttributeMaxDynamicSharedMemorySize, GEMM_SMEM);

    dim3 blk(256);
    int warpgridV = cdiv(V * 32, 256);
    int warpgridE = cdiv(E * 32, 256);

    // weight offsets (u32 units)
    const int OFF_ET = 0;
    const int OFF_G0IH = 20000;
    const int OFF_G0HH = 80000;
    const int OFF_LAYER = 140000;
    const int LAYER_STRIDE = 140000;

    convw_kernel<<<cdiv(20000, 256), blk>>>(et_W, wb + OFF_ET, 200, 200);
    convw_kernel<<<cdiv(60000, 256), blk>>>(gru0_Wih, wb + OFF_G0IH, 200, 600);
    convw_kernel<<<cdiv(60000, 256), blk>>>(gru0_Whh, wb + OFF_G0HH, 200, 600);
    for (int l = 0; l < L; l++) {
        convw_kernel<<<cdiv(20000, 256), blk>>>(gnn_pn_W + (long)l * 200 * 200,
                                                wb + OFF_LAYER + l * LAYER_STRIDE, 200, 200);
        convw_kernel<<<cdiv(60000, 256), blk>>>(gnn_gru_Wih + (long)l * 200 * 600,
                                                wb + OFF_LAYER + l * LAYER_STRIDE + 20000, 200, 600);
        convw_kernel<<<cdiv(60000, 256), blk>>>(gnn_gru_Whh + (long)l * 200 * 600,
                                                wb + OFF_LAYER + l * LAYER_STRIDE + 80000, 200, 600);
    }

    // CSR build
    fill_i_kernel<<<cdiv(V + 1, 256), blk>>>(rowptr, 0, V + 1);
    hist_kernel<<<cdiv(E, 256), blk>>>(dsti, rowptr, E);
    scan_kernel<<<1, 1024>>>(rowptr, V + 1);
    copy_i_kernel<<<cdiv(V, 256), blk>>>(rowptr, cursor, V);
    csr_scatter_kernel<<<cdiv(E, 256), blk>>>(dsti, cursor, csr, E);

    mask_kernel<<<cdiv(V, 256), blk>>>(node_feats, maskp, V);

    // hvb = bf16(lrelu(node_feats @ pn_W + b))
    {
        dim3 g(cdiv(GG, BN), cdiv(V, BM));
        mma_smallk_kernel<0><<<g, blk>>>(node_feats, NFEAT, pn_W, pn_b, hvb,
                                         V, GG, NFEAT, nullptr, nullptr, nullptr);
    }
    // he1b = bf16(lrelu(concat @ pe1_W + b))
    {
        dim3 g(cdiv(GG, BN), cdiv(E, BM));
        mma_smallk_kernel<2><<<g, blk>>>(nullptr, 0, pe1_W, pe1_b, he1b,
                                         E, GG, NFEAT + NEFEAT, node_feats, edge_feats, srci);
    }
    node_dots_kernel<<<warpgridV, blk>>>(hvb, pe2_W, d0, V);
    edge_ctx_logit_kernel<<<warpgridE, blk>>>(he1b, pe2_W + GG, pe2_b, d0, dsti, logit, E);
    softmax_csr_kernel<<<warpgridV, blk>>>(logit, rowptr, csr, att, V);
    // he2b = he1b @ et_W + b
    {
        dim3 g(cdiv(GG, BN), cdiv(E, BM));
        mma_bf16_kernel<<<g, dim3(128), GEMM_SMEM>>>(he1b, wb + OFF_ET, et_b, he2b, E, GG, GG);
    }
    gather_c_kernel<<<warpgridV, blk>>>(he2b, att, rowptr, csr, nullptr, cb, V);
    // GRU0
    {
        dim3 g(cdiv(3 * GG, BN), cdiv(V, BM));
        mma_bf16_kernel<<<g, dim3(128), GEMM_SMEM>>>(cb, wb + OFF_G0IH, gru0_bih, gib, V, 3 * GG, GG);
        mma_bf16_kernel<<<g, dim3(128), GEMM_SMEM>>>(hvb, wb + OFF_G0HH, gru0_bhh, ghb, V, 3 * GG, GG);
    }
    if (L > 0)
        gru_gates_fused<<<warpgridV, blk>>>(gib, ghb, hvb, gnn_pe_W, gnn_pe_W + GG,
                                            d0, d1, nullptr, nullptr, nullptr, nullptr, nullptr, V, 0);
    else {
        fill_f_kernel<<<cdiv(NG, 256), blk>>>(gsum, 0.f, NG);
        gru_gates_fused<<<warpgridV, blk>>>(gib, ghb, hvb, pred_W, nullptr, nullptr, nullptr,
                                            pred_b, maskp, gids, out + NG, gsum, V, 1);
    }

    for (int l = 0; l < L; l++) {
        edge_layer_logit_kernel<<<cdiv(E, 256), blk>>>(d0, d1, srci, dsti, gnn_pe_b + l, logit, E);
        softmax_csr_kernel<<<warpgridV, blk>>>(logit, rowptr, csr, att, V);
        {
            dim3 g(cdiv(GG, BN), cdiv(V, BM));
            mma_bf16_kernel<<<g, dim3(128), GEMM_SMEM>>>(hvb, wb + OFF_LAYER + l * LAYER_STRIDE,
                                                         gnn_pn_b + (long)l * GG, hvpb, V, GG, GG);
        }
        gather_c_kernel<<<warpgridV, blk>>>(hvpb, att, rowptr, csr, srci, cb, V);
        {
            dim3 g(cdiv(3 * GG, BN), cdiv(V, BM));
            mma_bf16_kernel<<<g, dim3(128), GEMM_SMEM>>>(cb, wb + OFF_LAYER + l * LAYER_STRIDE + 20000,
                                                         gnn_gru_bih + (long)l * 3 * GG, gib, V, 3 * GG, GG);
            mma_bf16_kernel<<<g, dim3(128), GEMM_SMEM>>>(hvb, wb + OFF_LAYER + l * LAYER_STRIDE + 80000,
                                                         gnn_gru_bhh + (long)l * 3 * GG, ghb, V, 3 * GG, GG);
        }
        if (l + 1 < L)
            gru_gates_fused<<<warpgridV, blk>>>(gib, ghb, hvb,
                                                gnn_pe_W + (long)(l + 1) * 2 * GG,
                                                gnn_pe_W + (long)(l + 1) * 2 * GG + GG,
                                                d0, d1, nullptr, nullptr, nullptr, nullptr, nullptr, V, 0);
        else {
            fill_f_kernel<<<cdiv(NG, 256), blk>>>(gsum, 0.f, NG);
            gru_gates_fused<<<warpgridV, blk>>>(gib, ghb, hvb, pred_W, nullptr, nullptr, nullptr,
                                                pred_b, maskp, gids, out + NG, gsum, V, 1);
        }
    }

    final_kernel<<<cdiv(NG, 256), blk>>>(gsum, out, NG);
}